// round 1
// baseline (speedup 1.0000x reference)
#include <cuda_runtime.h>
#include <cstdint>

#define Bsz 256
#define Lsz 500
#define Dsz 3
#define Csz 32
#define Isz 35
#define Hsz 512
#define Msz 5
#define Osz 15
#define Jsz 35
#define NC  50
#define LC  10
#define BH  (Bsz*Hsz)   /* 131072 */

// Scratch (allowed: __device__ globals). c / h (in place): [L][B][H]
__device__ float g_c[(size_t)Lsz * BH];   // 262 MB
__device__ float g_S[(size_t)NC  * BH];   // chunk sums
__device__ float g_P[(size_t)NC  * BH];   // chunk carries (b_enc + prefix)

using u64 = unsigned long long;

__device__ __forceinline__ u64 splat2(float x) {
    u64 r; unsigned u = __float_as_uint(x);
    asm("mov.b64 %0, {%1, %1};" : "=l"(r) : "r"(u));
    return r;
}
__device__ __forceinline__ u64 fma2(u64 a, u64 b, u64 c) {
    u64 d; asm("fma.rn.f32x2 %0, %1, %2, %3;" : "=l"(d) : "l"(a), "l"(b), "l"(c));
    return d;
}
__device__ __forceinline__ u64 add2(u64 a, u64 b) {
    u64 d; asm("add.rn.f32x2 %0, %1, %2;" : "=l"(d) : "l"(a), "l"(b));
    return d;
}
__device__ __forceinline__ void unpack2(u64 a, float& lo, float& hi) {
    unsigned x, y;
    asm("mov.b64 {%0, %1}, %2;" : "=r"(x), "=r"(y) : "l"(a));
    lo = __uint_as_float(x); hi = __uint_as_float(y);
}

// ---------------------------------------------------------------------------
// K1: encoder. Block = (chunk k, 32-row btile). Computes c[l] for the 10 l's
// of the chunk (written to g_c) and the chunk sum S (kept in registers).
// Thread tile: 4 b (bg = warp) x 16 h as 8 f32x2 pairs, h = 2*hg + 64*p + e.
// ---------------------------------------------------------------------------
__global__ void __launch_bounds__(256) k_encode(const float* __restrict__ inp,
                                                const float* __restrict__ zz,
                                                const float* __restrict__ W)
{
    extern __shared__ __align__(16) float smem[];
    float* ws = smem;               // [35][512]
    float* xs = smem + Isz * Hsz;   // [32][36]
    const int tid = threadIdx.x;
    const int k   = blockIdx.x;
    const int b0  = blockIdx.y * 32;
    const int bg  = tid >> 5;       // 0..7 (warp id)
    const int hg  = tid & 31;       // 0..31 (lane)

    u64 s2[4][8];
#pragma unroll
    for (int r = 0; r < 4; r++)
#pragma unroll
        for (int p = 0; p < 8; p++) s2[r][p] = 0ull;

    for (int t = 0; t < LC; t++) {
        const int l = k * LC + t;
        // load W_enc[l] (35x512 = 71.7 KB) cooperatively via float4
        {
            const float4* wsrc = (const float4*)(W + (size_t)l * (Isz * Hsz));
            float4* wdst = (float4*)ws;
#pragma unroll 4
            for (int u = tid; u < (Isz * Hsz) / 4; u += 256) wdst[u] = wsrc[u];
        }
        // load x tile: x[b][i] = concat(inputs[b][l][:3], z[b][l][:32])
        for (int u = tid; u < 32 * Isz; u += 256) {
            int b = u / Isz, i = u % Isz;
            float v = (i < Dsz)
                ? inp[(size_t)(b0 + b) * (Lsz * Dsz) + (size_t)l * Dsz + i]
                : zz [(size_t)(b0 + b) * (Lsz * Csz) + (size_t)l * Csz + (i - Dsz)];
            xs[b * 36 + i] = v;
        }
        __syncthreads();

        u64 c2[4][8];
#pragma unroll
        for (int r = 0; r < 4; r++)
#pragma unroll
            for (int p = 0; p < 8; p++) c2[r][p] = 0ull;

        for (int i = 0; i < Isz; i++) {
            u64 xd[4];
#pragma unroll
            for (int r = 0; r < 4; r++) xd[r] = splat2(xs[(bg * 4 + r) * 36 + i]);
#pragma unroll
            for (int p = 0; p < 8; p++) {
                u64 w2 = *(const u64*)&ws[i * Hsz + 2 * hg + 64 * p];
#pragma unroll
                for (int r = 0; r < 4; r++) c2[r][p] = fma2(xd[r], w2, c2[r][p]);
            }
        }

        float* cb = g_c + (size_t)l * BH + (size_t)b0 * Hsz;
#pragma unroll
        for (int r = 0; r < 4; r++)
#pragma unroll
            for (int p = 0; p < 8; p++) {
                *(u64*)&cb[(bg * 4 + r) * Hsz + 2 * hg + 64 * p] = c2[r][p];
                s2[r][p] = add2(s2[r][p], c2[r][p]);
            }
        __syncthreads();   // before ws is overwritten next l
    }

    float* sb = g_S + (size_t)k * BH + (size_t)b0 * Hsz;
#pragma unroll
    for (int r = 0; r < 4; r++)
#pragma unroll
        for (int p = 0; p < 8; p++)
            *(u64*)&sb[(bg * 4 + r) * Hsz + 2 * hg + 64 * p] = s2[r][p];
}

// ---------------------------------------------------------------------------
// K2: scan chunk sums. P[k] = b_enc + sum_{j<k} S[j]. One thread per (b,h).
// ---------------------------------------------------------------------------
__global__ void k_scan(const float* __restrict__ benc)
{
    const int idx = blockIdx.x * 256 + threadIdx.x;   // 0..131071, = b*512 + h
    float run = benc[idx & (Hsz - 1)];
#pragma unroll 5
    for (int k = 0; k < NC; k++) {
        g_P[(size_t)k * BH + idx] = run;
        run += g_S[(size_t)k * BH + idx];
    }
}

// ---------------------------------------------------------------------------
// K3a: apply exclusive prefix within each chunk; rewrite g_c in place with
// h[l] = relu(a[l]). Each thread owns 64 strided (b,h) slots (coalesced).
// ---------------------------------------------------------------------------
__global__ void __launch_bounds__(256) k_prefix()
{
    const int k  = blockIdx.x;
    const int b0 = blockIdx.y * 32;
    const int tid = threadIdx.x;
    const size_t base = (size_t)b0 * Hsz;

    float acc[64];
    const float* P = g_P + (size_t)k * BH + base;
#pragma unroll
    for (int q = 0; q < 64; q++) acc[q] = P[q * 256 + tid];

    for (int t = 0; t < LC; t++) {
        const int l = k * LC + t;
        float* cp = g_c + (size_t)l * BH + base;
        float cv[64];
#pragma unroll
        for (int q = 0; q < 64; q++) cv[q] = cp[q * 256 + tid];
#pragma unroll
        for (int q = 0; q < 64; q++) {
            cp[q * 256 + tid] = fmaxf(acc[q], 0.0f);   // h[l] = relu(a[l])
            acc[q] += cv[q];                            // a[l+1]
        }
    }
}

// ---------------------------------------------------------------------------
// K3b: decoder. Block = (l, 128-row btile), 160 threads = 32 bgroups x 5 jgroups.
// Thread tile 4b x 8j (4 f32x2 pairs). V packed as vs[h][40] (35 cols + zero pad).
// ---------------------------------------------------------------------------
__global__ void __launch_bounds__(160) k_decode(const float* __restrict__ Vmu,
                                                const float* __restrict__ bmu,
                                                const float* __restrict__ Vsg,
                                                const float* __restrict__ bsg,
                                                const float* __restrict__ Vpi,
                                                const float* __restrict__ bpi,
                                                float* __restrict__ out)
{
    extern __shared__ __align__(16) float smem[];
    float* vs   = smem;                    // [512][40]
    float* hs   = smem + Hsz * 40;         // [128][65]
    float* bias = hs + 128 * 65;           // [40]
    const int tid = threadIdx.x;
    const int l   = blockIdx.x;
    const int bt0 = blockIdx.y * 128;

    // pack V_mu|V_sigma|V_pi into vs[h][j], j: 0..14 mu, 15..29 sigma, 30..34 pi
    for (int u = tid; u < Hsz * 40; u += 160) {
        int h = u / 40, jc = u % 40;
        float v;
        if (jc < 15)      v = Vmu[(size_t)l * (Hsz * Osz) + h * Osz + jc];
        else if (jc < 30) v = Vsg[(size_t)l * (Hsz * Osz) + h * Osz + (jc - 15)];
        else if (jc < 35) v = Vpi[(size_t)l * (Hsz * Msz) + h * Msz + (jc - 30)];
        else              v = 0.0f;
        vs[u] = v;
    }
    if (tid < 40) {
        int jc = tid; float v;
        if (jc < 15)      v = bmu[(size_t)l * Osz + jc];
        else if (jc < 30) v = bsg[(size_t)l * Osz + (jc - 15)];
        else if (jc < 35) v = bpi[(size_t)l * Msz + (jc - 30)];
        else              v = 0.0f;
        bias[jc] = v;
    }

    const int jg = tid % 5;     // 0..4 -> j base jg*8
    const int bg = tid / 5;     // 0..31 -> b base bg*4
    u64 acc2[4][4];
#pragma unroll
    for (int r = 0; r < 4; r++)
#pragma unroll
        for (int u4 = 0; u4 < 4; u4++) acc2[r][u4] = 0ull;

    const float* hbase = g_c + (size_t)l * BH + (size_t)bt0 * Hsz;

    for (int kk = 0; kk < Hsz; kk += 64) {
        // stage h tile [128 b][64 k] (already relu'd by k_prefix)
        for (int u = tid; u < 128 * 16; u += 160) {
            int b = u >> 4, kq = u & 15;
            float4 v = *(const float4*)&hbase[(size_t)b * Hsz + kk + kq * 4];
            float* d = &hs[b * 65 + kq * 4];
            d[0] = v.x; d[1] = v.y; d[2] = v.z; d[3] = v.w;
        }
        __syncthreads();   // also orders the vs/bias fill before first use

#pragma unroll 4
        for (int k2 = 0; k2 < 64; k2++) {
            u64 hv[4];
#pragma unroll
            for (int r = 0; r < 4; r++) hv[r] = splat2(hs[(bg * 4 + r) * 65 + k2]);
#pragma unroll
            for (int u4 = 0; u4 < 4; u4++) {
                u64 v2 = *(const u64*)&vs[(kk + k2) * 40 + jg * 8 + u4 * 2];
#pragma unroll
                for (int r = 0; r < 4; r++) acc2[r][u4] = fma2(hv[r], v2, acc2[r][u4]);
            }
        }
        __syncthreads();   // before hs is overwritten
    }

#pragma unroll
    for (int r = 0; r < 4; r++) {
        const int b = bt0 + bg * 4 + r;
#pragma unroll
        for (int u4 = 0; u4 < 4; u4++) {
            float lo, hi; unpack2(acc2[r][u4], lo, hi);
            const int j0 = jg * 8 + u4 * 2;
            if (j0 < Jsz)
                out[(size_t)b * (Lsz * Jsz) + (size_t)l * Jsz + j0]     = lo + bias[j0];
            if (j0 + 1 < Jsz)
                out[(size_t)b * (Lsz * Jsz) + (size_t)l * Jsz + j0 + 1] = hi + bias[j0 + 1];
        }
    }
}

// ---------------------------------------------------------------------------
extern "C" void kernel_launch(void* const* d_in, const int* in_sizes, int n_in,
                              void* d_out, int out_size)
{
    const float* inp  = (const float*)d_in[0];   // inputs [B,L,D]
    const float* zz   = (const float*)d_in[1];   // z      [B,L,C]
    const float* W    = (const float*)d_in[2];   // W_enc  [L,I,H]
    const float* benc = (const float*)d_in[3];   // b_enc  [1,H]
    const float* Vmu  = (const float*)d_in[4];   // V_mu   [L,H,O]
    const float* bmu  = (const float*)d_in[5];   // b_mu   [L,1,O]
    const float* Vsg  = (const float*)d_in[6];   // V_sigma
    const float* bsg  = (const float*)d_in[7];
    const float* Vpi  = (const float*)d_in[8];   // V_pi   [L,H,M]
    const float* bpi  = (const float*)d_in[9];
    float* out = (float*)d_out;                  // [B,L,35]

    const int sm1 = (Isz * Hsz + 32 * 36) * (int)sizeof(float);            // 76288
    const int sm3 = (Hsz * 40 + 128 * 65 + 40) * (int)sizeof(float);       // 115360
    cudaFuncSetAttribute(k_encode, cudaFuncAttributeMaxDynamicSharedMemorySize, sm1);
    cudaFuncSetAttribute(k_decode, cudaFuncAttributeMaxDynamicSharedMemorySize, sm3);

    k_encode<<<dim3(NC, Bsz / 32), 256, sm1>>>(inp, zz, W);
    k_scan  <<<BH / 256, 256>>>(benc);
    k_prefix<<<dim3(NC, Bsz / 32), 256>>>();
    k_decode<<<dim3(Lsz, Bsz / 128), 160, sm3>>>(Vmu, bmu, Vsg, bsg, Vpi, bpi, out);
}

// round 2
// speedup vs baseline: 1.0367x; 1.0367x over previous
#include <cuda_runtime.h>
#include <cstdint>

#define Bsz 256
#define Lsz 500
#define Dsz 3
#define Csz 32
#define Isz 35
#define Hsz 512
#define Msz 5
#define Osz 15
#define Jsz 35
#define NC  50
#define LC  10
#define BH  (Bsz*Hsz)   /* 131072 */
#define BL  (Bsz*Lsz)   /* 128000 */
#define NSL 4           /* h slices */
#define HS  (Hsz/NSL)   /* 128 */

// Scratch (device globals are allowed)
__device__ float g_c[(size_t)Lsz * BH];          // 262 MB  per-step contributions
__device__ float g_S[(size_t)NC  * BH];          // chunk sums
__device__ float g_P[(size_t)NC  * BH];          // chunk carries (b_enc + prefix)
__device__ float g_part[(size_t)NSL * BL * 40];  // 82 MB   per-slice decode partials

using u64 = unsigned long long;

__device__ __forceinline__ u64 splat2(float x) {
    u64 r; unsigned u = __float_as_uint(x);
    asm("mov.b64 %0, {%1, %1};" : "=l"(r) : "r"(u));
    return r;
}
__device__ __forceinline__ u64 fma2(u64 a, u64 b, u64 c) {
    u64 d; asm("fma.rn.f32x2 %0, %1, %2, %3;" : "=l"(d) : "l"(a), "l"(b), "l"(c));
    return d;
}
__device__ __forceinline__ u64 add2(u64 a, u64 b) {
    u64 d; asm("add.rn.f32x2 %0, %1, %2;" : "=l"(d) : "l"(a), "l"(b));
    return d;
}

// ---------------------------------------------------------------------------
// K1: encoder. Block = (chunk k, 32-row btile), 512 threads (16 warps).
// Thread tile: 2 b (warp) x 16 h (lane). Writes c[l] to g_c and chunk sum to g_S.
// ---------------------------------------------------------------------------
__global__ void __launch_bounds__(512) k_encode(const float* __restrict__ inp,
                                                const float* __restrict__ zz,
                                                const float* __restrict__ W)
{
    extern __shared__ __align__(16) float smem[];
    float* ws = smem;               // [35][512]
    float* xs = smem + Isz * Hsz;   // [32][36]
    const int tid  = threadIdx.x;
    const int k    = blockIdx.x;
    const int b0   = blockIdx.y * 32;
    const int w    = tid >> 5;      // 0..15 -> b pair 2w,2w+1
    const int lane = tid & 31;      // 0..31 -> h = 2*lane + 64*p

    u64 s2[2][8];
#pragma unroll
    for (int r = 0; r < 2; r++)
#pragma unroll
        for (int p = 0; p < 8; p++) s2[r][p] = 0ull;

    for (int t = 0; t < LC; t++) {
        const int l = k * LC + t;
        {   // stage W_enc[l] (71.7 KB)
            const float4* wsrc = (const float4*)(W + (size_t)l * (Isz * Hsz));
            float4* wdst = (float4*)ws;
            for (int u = tid; u < (Isz * Hsz) / 4; u += 512) wdst[u] = wsrc[u];
        }
        // stage x tile
        for (int u = tid; u < 32 * Isz; u += 512) {
            int b = u / Isz, i = u % Isz;
            float v = (i < Dsz)
                ? inp[(size_t)(b0 + b) * (Lsz * Dsz) + (size_t)l * Dsz + i]
                : zz [(size_t)(b0 + b) * (Lsz * Csz) + (size_t)l * Csz + (i - Dsz)];
            xs[b * 36 + i] = v;
        }
        __syncthreads();

        u64 c2[2][8];
#pragma unroll
        for (int r = 0; r < 2; r++)
#pragma unroll
            for (int p = 0; p < 8; p++) c2[r][p] = 0ull;

        for (int i = 0; i < Isz; i++) {
            u64 xd[2];
#pragma unroll
            for (int r = 0; r < 2; r++) xd[r] = splat2(xs[(2 * w + r) * 36 + i]);
#pragma unroll
            for (int p = 0; p < 8; p++) {
                u64 w2 = *(const u64*)&ws[i * Hsz + 2 * lane + 64 * p];
#pragma unroll
                for (int r = 0; r < 2; r++) c2[r][p] = fma2(xd[r], w2, c2[r][p]);
            }
        }

        float* cb = g_c + (size_t)l * BH + (size_t)b0 * Hsz;
#pragma unroll
        for (int r = 0; r < 2; r++)
#pragma unroll
            for (int p = 0; p < 8; p++) {
                *(u64*)&cb[(2 * w + r) * Hsz + 2 * lane + 64 * p] = c2[r][p];
                s2[r][p] = add2(s2[r][p], c2[r][p]);
            }
        __syncthreads();
    }

    float* sb = g_S + (size_t)k * BH + (size_t)b0 * Hsz;
#pragma unroll
    for (int r = 0; r < 2; r++)
#pragma unroll
        for (int p = 0; p < 8; p++)
            *(u64*)&sb[(2 * w + r) * Hsz + 2 * lane + 64 * p] = s2[r][p];
}

// ---------------------------------------------------------------------------
// K2: scan chunk sums. P[k] = b_enc + sum_{j<k} S[j].
// ---------------------------------------------------------------------------
__global__ void k_scan(const float* __restrict__ benc)
{
    const int idx = blockIdx.x * 256 + threadIdx.x;   // = b*512 + h
    float run = benc[idx & (Hsz - 1)];
#pragma unroll 5
    for (int k = 0; k < NC; k++) {
        g_P[(size_t)k * BH + idx] = run;
        run += g_S[(size_t)k * BH + idx];
    }
}

// ---------------------------------------------------------------------------
// K3: fused prefix + decode. Block = (chunk k, 128-b tile, 128-h slice).
// 128 threads = 32 bg (4 b) x 4 jg (10 j). Running accumulator a[b][h] lives in
// smem; per step t: stage V[l] slice, decode relu(acc), then acc += c[l].
// ---------------------------------------------------------------------------
__global__ void __launch_bounds__(128) k_fused(const float* __restrict__ Vmu,
                                               const float* __restrict__ Vsg,
                                               const float* __restrict__ Vpi)
{
    extern __shared__ __align__(16) float smem[];
    float* acc = smem;                 // [128][129]
    float* vs  = smem + 128 * 129;     // [128][40]
    const int tid = threadIdx.x;
    const int k   = blockIdx.x;
    const int b0  = blockIdx.y * 128;
    const int h0  = blockIdx.z * HS;
    const int s   = blockIdx.z;
    const int bg  = tid >> 2;          // 0..31
    const int jg  = tid & 3;           // 0..3

    // init acc from carry P[k] (bank-conflict-free mapping: col = jg + 4q)
    {
        const float* P = g_P + (size_t)k * BH + (size_t)b0 * Hsz + h0;
#pragma unroll
        for (int r = 0; r < 4; r++) {
            const int row = 4 * bg + r;
#pragma unroll 8
            for (int q = 0; q < 32; q++)
                acc[row * 129 + jg + 4 * q] = P[(size_t)row * Hsz + jg + 4 * q];
        }
    }

    for (int t = 0; t < LC; t++) {
        const int l = k * LC + t;
        __syncthreads();   // prev decode reads + acc writes done; safe to restage vs
        // stage V[l] slice packed as vs[h][40]: 0..14 mu, 15..29 sigma, 30..34 pi
        for (int u = tid; u < HS * 40; u += 128) {
            int h = u / 40, jc = u % 40;
            int hh = h0 + h;
            float v = 0.0f;
            if (jc < 15)      v = Vmu[(size_t)l * (Hsz * Osz) + hh * Osz + jc];
            else if (jc < 30) v = Vsg[(size_t)l * (Hsz * Osz) + hh * Osz + (jc - 15)];
            else if (jc < 35) v = Vpi[(size_t)l * (Hsz * Msz) + hh * Msz + (jc - 30)];
            vs[u] = v;
        }
        __syncthreads();

        // decode: o[4b][10j] += relu(acc) @ vs over 128 h
        u64 o2[4][5];
#pragma unroll
        for (int r = 0; r < 4; r++)
#pragma unroll
            for (int u = 0; u < 5; u++) o2[r][u] = 0ull;

#pragma unroll 4
        for (int h = 0; h < HS; h++) {
            u64 hv[4];
#pragma unroll
            for (int r = 0; r < 4; r++)
                hv[r] = splat2(fmaxf(acc[(4 * bg + r) * 129 + h], 0.0f));
#pragma unroll
            for (int u = 0; u < 5; u++) {
                u64 v2 = *(const u64*)&vs[h * 40 + jg * 10 + 2 * u];
#pragma unroll
                for (int r = 0; r < 4; r++) o2[r][u] = fma2(hv[r], v2, o2[r][u]);
            }
        }

        // write partials: g_part[s][(b*L+l)][40]
#pragma unroll
        for (int r = 0; r < 4; r++) {
            const size_t pair = (size_t)(b0 + 4 * bg + r) * Lsz + l;
            float* dst = g_part + ((size_t)s * BL + pair) * 40 + jg * 10;
#pragma unroll
            for (int u = 0; u < 5; u++) *(u64*)&dst[2 * u] = o2[r][u];
        }

        __syncthreads();   // all decode reads of acc complete before update
        // acc += c[l] (slice)
        const float* cb = g_c + (size_t)l * BH + (size_t)b0 * Hsz + h0;
#pragma unroll
        for (int r = 0; r < 4; r++) {
            const int row = 4 * bg + r;
#pragma unroll 8
            for (int q = 0; q < 32; q++)
                acc[row * 129 + jg + 4 * q] += cb[(size_t)row * Hsz + jg + 4 * q];
        }
    }
}

// ---------------------------------------------------------------------------
// K4: reduce slices + add output biases. Block = 280 threads = 8 (b,l) pairs x 35 j.
// ---------------------------------------------------------------------------
__global__ void __launch_bounds__(280) k_reduce(const float* __restrict__ bmu,
                                                const float* __restrict__ bsg,
                                                const float* __restrict__ bpi,
                                                float* __restrict__ out)
{
    const int p = threadIdx.x / 35;
    const int j = threadIdx.x % 35;
    const size_t pair = (size_t)blockIdx.x * 8 + p;   // = b*500 + l
    const int l = (int)(pair % Lsz);

    float v = 0.0f;
#pragma unroll
    for (int s = 0; s < NSL; s++)
        v += g_part[((size_t)s * BL + pair) * 40 + j];

    float bias;
    if (j < 15)      bias = bmu[l * Osz + j];
    else if (j < 30) bias = bsg[l * Osz + (j - 15)];
    else             bias = bpi[l * Msz + (j - 30)];

    out[pair * Jsz + j] = v + bias;
}

// ---------------------------------------------------------------------------
extern "C" void kernel_launch(void* const* d_in, const int* in_sizes, int n_in,
                              void* d_out, int out_size)
{
    const float* inp  = (const float*)d_in[0];
    const float* zz   = (const float*)d_in[1];
    const float* W    = (const float*)d_in[2];
    const float* benc = (const float*)d_in[3];
    const float* Vmu  = (const float*)d_in[4];
    const float* bmu  = (const float*)d_in[5];
    const float* Vsg  = (const float*)d_in[6];
    const float* bsg  = (const float*)d_in[7];
    const float* Vpi  = (const float*)d_in[8];
    const float* bpi  = (const float*)d_in[9];
    float* out = (float*)d_out;

    const int sm1 = (Isz * Hsz + 32 * 36) * (int)sizeof(float);        // 76288
    const int sm3 = (128 * 129 + 128 * 40) * (int)sizeof(float);       // 86528
    cudaFuncSetAttribute(k_encode, cudaFuncAttributeMaxDynamicSharedMemorySize, sm1);
    cudaFuncSetAttribute(k_fused,  cudaFuncAttributeMaxDynamicSharedMemorySize, sm3);

    k_encode<<<dim3(NC, Bsz / 32), 512, sm1>>>(inp, zz, W);
    k_scan  <<<BH / 256, 256>>>(benc);
    k_fused <<<dim3(NC, Bsz / 128, NSL), 128, sm3>>>(Vmu, Vsg, Vpi);
    k_reduce<<<BL / 8, 280>>>(bmu, bsg, bpi, out);
}

// round 4
// speedup vs baseline: 1.3601x; 1.3119x over previous
#include <cuda_runtime.h>
#include <cstdint>

#define Bsz 256
#define Lsz 500
#define Dsz 3
#define Csz 32
#define Isz 35
#define Hsz 512
#define Msz 5
#define Osz 15
#define Jsz 35
#define NC  50
#define LC  10
#define BH  (Bsz*Hsz)   /* 131072 */
#define BL  (Bsz*Lsz)   /* 128000 */
#define NSL 4           /* h slices */
#define HS  (Hsz/NSL)   /* 128 */
#define BT  64          /* b tile in k_all */
#define NBT (Bsz/BT)    /* 4 */

// Scratch (device globals are allowed)
__device__ __align__(16) float g_S[(size_t)NC * BH];           // chunk sums      26 MB
__device__ __align__(16) float g_P[(size_t)NC * BH];           // chunk carries   26 MB
__device__ __align__(16) float g_part[(size_t)NSL * BL * 40];  // decode partials 82 MB

using u64 = unsigned long long;

__device__ __forceinline__ u64 splat2(float x) {
    u64 r; unsigned u = __float_as_uint(x);
    asm("mov.b64 %0, {%1, %1};" : "=l"(r) : "r"(u));
    return r;
}
__device__ __forceinline__ u64 fma2(u64 a, u64 b, u64 c) {
    u64 d; asm("fma.rn.f32x2 %0, %1, %2, %3;" : "=l"(d) : "l"(a), "l"(b), "l"(c));
    return d;
}

// ---------------------------------------------------------------------------
// K1: chunk sums only. Block = (btile 32 [x], chunk k [y]). 512 threads;
// thread owns 1 b x 32 h (be = tid&31, hg = tid>>5 warp-uniform).
// acc (= S) lives in registers across the 10 steps; c never stored.
// ---------------------------------------------------------------------------
__global__ void __launch_bounds__(512) k_sums(const float* __restrict__ inp,
                                              const float* __restrict__ zz,
                                              const float* __restrict__ W)
{
    extern __shared__ __align__(16) float smem[];
    float* ws = smem;               // [35][512]
    float* xs = smem + Isz * Hsz;   // [32][36]
    const int tid = threadIdx.x;
    const int b0  = blockIdx.x * 32;
    const int k   = blockIdx.y;
    const int be  = tid & 31;
    const int hg  = tid >> 5;       // 0..15, warp-uniform -> w2 loads broadcast

    u64 acc[16];
#pragma unroll
    for (int p = 0; p < 16; p++) acc[p] = 0ull;

    for (int t = 0; t < LC; t++) {
        const int l = k * LC + t;
        {
            const float4* wsrc = (const float4*)(W + (size_t)l * (Isz * Hsz));
            float4* wdst = (float4*)ws;
            for (int u = tid; u < (Isz * Hsz) / 4; u += 512) wdst[u] = wsrc[u];
        }
        for (int u = tid; u < 32 * Isz; u += 512) {
            int b = u / Isz, i = u % Isz;
            xs[b * 36 + i] = (i < Dsz)
                ? inp[(size_t)(b0 + b) * (Lsz * Dsz) + (size_t)l * Dsz + i]
                : zz [(size_t)(b0 + b) * (Lsz * Csz) + (size_t)l * Csz + (i - Dsz)];
        }
        __syncthreads();

        for (int i = 0; i < Isz; i++) {
            u64 xd = splat2(xs[be * 36 + i]);
#pragma unroll
            for (int p = 0; p < 16; p++) {
                u64 w2 = *(const u64*)&ws[i * Hsz + hg * 32 + 2 * p];
                acc[p] = fma2(xd, w2, acc[p]);
            }
        }
        __syncthreads();
    }

    // transpose through smem (ws is free) for coalesced S store.
    // STRIDE 516 (multiple of 4!) so float4 reads below stay 16B-aligned.
    float* tb = ws;   // [32][516] = 16512 floats < 19072 available
#pragma unroll
    for (int p = 0; p < 16; p++)
        *(u64*)&tb[be * 516 + hg * 32 + 2 * p] = acc[p];
    __syncthreads();
    float* sb = g_S + (size_t)k * BH + (size_t)b0 * Hsz;
    for (int u = tid; u < 32 * (Hsz / 4); u += 512) {   // 4096 float4
        int b = u >> 7, c4 = u & 127;
        *(float4*)&sb[(size_t)b * Hsz + c4 * 4] = *(const float4*)&tb[b * 516 + c4 * 4];
    }
}

// ---------------------------------------------------------------------------
// K2: scan chunk sums. P[k] = b_enc + sum_{j<k} S[j].
// ---------------------------------------------------------------------------
__global__ void k_scan(const float* __restrict__ benc)
{
    const int idx = blockIdx.x * 256 + threadIdx.x;
    float run = benc[idx & (Hsz - 1)];
#pragma unroll 5
    for (int k = 0; k < NC; k++) {
        g_P[(size_t)k * BH + idx] = run;
        run += g_S[(size_t)k * BH + idx];
    }
}

// ---------------------------------------------------------------------------
// K3: fully fused encode+prefix+decode, h-sliced. Block =
// (x = btile*NSL + hslice [16 per chunk], y = chunk k). 256 threads.
// Encoder: thread = 1 b x 32 h (be = tid&63, hg = tid>>6 warp-uniform),
// running accumulator a in REGISTERS; relu(a) published via smem hs.
// Decoder: thread = 1 b x 10 j (bq = tid>>2, jg = tid&3).
// ---------------------------------------------------------------------------
__global__ void __launch_bounds__(256) k_all(const float* __restrict__ inp,
                                             const float* __restrict__ zz,
                                             const float* __restrict__ W,
                                             const float* __restrict__ Vmu,
                                             const float* __restrict__ Vsg,
                                             const float* __restrict__ Vpi)
{
    extern __shared__ __align__(16) float smem[];
    float* ws = smem;                       // [35][128]   17.5 KB
    float* vs = ws + Isz * HS;              // [128][40]   20 KB
    float* hs = vs + HS * 40;               // [64][130]   33.3 KB
    float* xs = hs + BT * 130;              // [64][36]     9.2 KB
    const int tid = threadIdx.x;
    const int bt  = blockIdx.x / NSL;
    const int s   = blockIdx.x % NSL;
    const int k   = blockIdx.y;
    const int b0  = bt * BT;
    const int h0  = s * HS;
    const int be  = tid & 63;
    const int hg  = tid >> 6;       // 0..3, warp-uniform
    const int bq  = tid >> 2;       // 0..63
    const int jg  = tid & 3;        // 0..3

    // init a from carry P (registers) and publish relu to hs
    u64 acc[16];
    {
        const float* P = g_P + (size_t)k * BH + (size_t)(b0 + be) * Hsz + h0 + hg * 32;
#pragma unroll
        for (int p = 0; p < 16; p++) {
            float2 v = *(const float2*)&P[2 * p];
            acc[p] = *(const u64*)&v;
            float2 r2 = make_float2(fmaxf(v.x, 0.0f), fmaxf(v.y, 0.0f));
            *(float2*)&hs[be * 130 + hg * 32 + 2 * p] = r2;
        }
    }

    for (int t = 0; t < LC; t++) {
        const int l = k * LC + t;
        __syncthreads();   // hs init / prev-step hs writes visible; stage buffers free
        // stage W slice [35][128]
        {
            const float4* wsrc = (const float4*)(W + (size_t)l * (Isz * Hsz) + h0);
            for (int u = tid; u < Isz * (HS / 4); u += 256) {
                int row = u >> 5, col = u & 31;
                ((float4*)ws)[u] = wsrc[row * (Hsz / 4) + col];
            }
        }
        // stage V slice packed [128][40]: 0..14 mu, 15..29 sigma, 30..34 pi
        for (int u = tid; u < HS * 40; u += 256) {
            int h = u / 40, jc = u % 40;
            int hh = h0 + h;
            float v = 0.0f;
            if (jc < 15)      v = Vmu[(size_t)l * (Hsz * Osz) + hh * Osz + jc];
            else if (jc < 30) v = Vsg[(size_t)l * (Hsz * Osz) + hh * Osz + (jc - 15)];
            else if (jc < 35) v = Vpi[(size_t)l * (Hsz * Msz) + hh * Msz + (jc - 30)];
            vs[u] = v;
        }
        // stage x tile [64][35]
        for (int u = tid; u < BT * Isz; u += 256) {
            int b = u / Isz, i = u % Isz;
            xs[b * 36 + i] = (i < Dsz)
                ? inp[(size_t)(b0 + b) * (Lsz * Dsz) + (size_t)l * Dsz + i]
                : zz [(size_t)(b0 + b) * (Lsz * Csz) + (size_t)l * Csz + (i - Dsz)];
        }
        __syncthreads();

        // ---- decode: out_part[l] = relu(a[l]) @ V[l]  (hs holds relu(a[l]))
        u64 o2[5];
#pragma unroll
        for (int u = 0; u < 5; u++) o2[u] = 0ull;
#pragma unroll 4
        for (int h = 0; h < HS; h++) {
            u64 hv = splat2(hs[bq * 130 + h]);
#pragma unroll
            for (int u = 0; u < 5; u++) {
                u64 v2 = *(const u64*)&vs[h * 40 + jg * 10 + 2 * u];
                o2[u] = fma2(hv, v2, o2[u]);
            }
        }
        {
            float* dst = g_part + ((size_t)s * BL + (size_t)(b0 + bq) * Lsz + l) * 40 + jg * 10;
#pragma unroll
            for (int u = 0; u < 5; u++) *(u64*)&dst[2 * u] = o2[u];
        }

        // ---- encode: a += x[l] @ W[l]  (register accumulator)
        for (int i = 0; i < Isz; i++) {
            u64 xd = splat2(xs[be * 36 + i]);
#pragma unroll
            for (int p = 0; p < 16; p++) {
                u64 w2 = *(const u64*)&ws[i * HS + hg * 32 + 2 * p];
                acc[p] = fma2(xd, w2, acc[p]);
            }
        }

        __syncthreads();   // all decode reads of hs complete
        // publish relu(a[l+1])
#pragma unroll
        for (int p = 0; p < 16; p++) {
            float2 v = *(const float2*)&acc[p];
            float2 r2 = make_float2(fmaxf(v.x, 0.0f), fmaxf(v.y, 0.0f));
            *(float2*)&hs[be * 130 + hg * 32 + 2 * p] = r2;
        }
    }
}

// ---------------------------------------------------------------------------
// K4: reduce slices + output biases. 280 threads = 8 (b,l) pairs x 35 j.
// ---------------------------------------------------------------------------
__global__ void __launch_bounds__(280) k_reduce(const float* __restrict__ bmu,
                                                const float* __restrict__ bsg,
                                                const float* __restrict__ bpi,
                                                float* __restrict__ out)
{
    const int p = threadIdx.x / 35;
    const int j = threadIdx.x % 35;
    const size_t pair = (size_t)blockIdx.x * 8 + p;   // = b*500 + l
    const int l = (int)(pair % Lsz);

    float v = 0.0f;
#pragma unroll
    for (int s = 0; s < NSL; s++)
        v += g_part[((size_t)s * BL + pair) * 40 + j];

    float bias;
    if (j < 15)      bias = bmu[l * Osz + j];
    else if (j < 30) bias = bsg[l * Osz + (j - 15)];
    else             bias = bpi[l * Msz + (j - 30)];

    out[pair * Jsz + j] = v + bias;
}

// ---------------------------------------------------------------------------
extern "C" void kernel_launch(void* const* d_in, const int* in_sizes, int n_in,
                              void* d_out, int out_size)
{
    const float* inp  = (const float*)d_in[0];
    const float* zz   = (const float*)d_in[1];
    const float* W    = (const float*)d_in[2];
    const float* benc = (const float*)d_in[3];
    const float* Vmu  = (const float*)d_in[4];
    const float* bmu  = (const float*)d_in[5];
    const float* Vsg  = (const float*)d_in[6];
    const float* bsg  = (const float*)d_in[7];
    const float* Vpi  = (const float*)d_in[8];
    const float* bpi  = (const float*)d_in[9];
    float* out = (float*)d_out;

    const int sm1 = (Isz * Hsz + 32 * 36) * (int)sizeof(float);                 // 76288
    const int sm3 = (Isz * HS + HS * 40 + BT * 130 + BT * 36) * (int)sizeof(float); // ~80 KB
    cudaFuncSetAttribute(k_sums, cudaFuncAttributeMaxDynamicSharedMemorySize, sm1);
    cudaFuncSetAttribute(k_all,  cudaFuncAttributeMaxDynamicSharedMemorySize, sm3);

    k_sums<<<dim3(Bsz / 32, NC), 512, sm1>>>(inp, zz, W);
    k_scan<<<BH / 256, 256>>>(benc);
    k_all <<<dim3(NBT * NSL, NC), 256, sm3>>>(inp, zz, W, Vmu, Vsg, Vpi);
    k_reduce<<<BL / 8, 280>>>(bmu, bsg, bpi, out);
}

// round 5
// speedup vs baseline: 1.8370x; 1.3506x over previous
#include <cuda_runtime.h>
#include <cstdint>

#define Bsz 256
#define Lsz 500
#define Dsz 3
#define Csz 32
#define Isz 35
#define Hsz 512
#define Msz 5
#define Osz 15
#define Jsz 35
#define NC  50
#define LC  10
#define BH  (Bsz*Hsz)   /* 131072 */
#define BL  (Bsz*Lsz)   /* 128000 */
#define NSL 4           /* h slices */
#define HS  (Hsz/NSL)   /* 128 */
#define BT  64          /* b tile */
#define NBT (Bsz/BT)    /* 4 */
#define HP  130         /* hs row stride */
#define XP  37          /* xs row stride (conflict-free) */

// Scratch (device globals are allowed)
__device__ __align__(16) float g_S[(size_t)NC * BH];           // chunk sums      26 MB
__device__ __align__(16) float g_P[(size_t)NC * BH];           // chunk carries   26 MB
__device__ __align__(16) float g_part[(size_t)NSL * BL * 40];  // decode partials 82 MB

using u64 = unsigned long long;

__device__ __forceinline__ u64 splat2(float x) {
    u64 r; unsigned u = __float_as_uint(x);
    asm("mov.b64 %0, {%1, %1};" : "=l"(r) : "r"(u));
    return r;
}
__device__ __forceinline__ u64 fma2(u64 a, u64 b, u64 c) {
    u64 d; asm("fma.rn.f32x2 %0, %1, %2, %3;" : "=l"(d) : "l"(a), "l"(b), "l"(c));
    return d;
}

// ---------------------------------------------------------------------------
// Shared staging helpers (W slice / x tile), used by k_sums and k_all.
// block tile: 64 b x 128 h. 256 threads.
// ---------------------------------------------------------------------------
__device__ __forceinline__ void stage_w(float* ws, const float* __restrict__ W,
                                        int l, int h0, int tid)
{
    const float4* src = (const float4*)(W + (size_t)l * (Isz * Hsz));
#pragma unroll
    for (int q = 0; q < 5; q++) {
        int idx = tid + 256 * q;
        if (idx < Isz * 32) {                 // 35 rows x 32 float4
            int row = idx >> 5, col = idx & 31;
            ((float4*)ws)[row * 32 + col] = src[row * 128 + (h0 >> 2) + col];
        }
    }
}
__device__ __forceinline__ void stage_x(float* xs, const float* __restrict__ inp,
                                        const float* __restrict__ zz,
                                        int l, int b0, int tid)
{
#pragma unroll
    for (int q = 0; q < 9; q++) {
        int u = tid + 256 * q;
        if (u < BT * Isz) {
            int b = u / Isz, i = u % Isz;
            xs[b * XP + i] = (i < Dsz)
                ? inp[(size_t)(b0 + b) * (Lsz * Dsz) + l * Dsz + i]
                : zz [(size_t)(b0 + b) * (Lsz * Csz) + l * Csz + (i - Dsz)];
        }
    }
}

// Encoder micro-kernel: acc[4b][4 u64 = 8h] += x @ Wslice.
// bg = tid>>4 (b group), hg = tid&15 (h: hg*2 + 32p + e).
__device__ __forceinline__ void encode_step(u64 acc[4][4], const float* ws,
                                            const float* xs, int bg, int hg)
{
#pragma unroll 7
    for (int i = 0; i < Isz; i++) {
        u64 xa[4], wv[4];
#pragma unroll
        for (int r = 0; r < 4; r++) xa[r] = splat2(xs[(bg * 4 + r) * XP + i]);
#pragma unroll
        for (int p = 0; p < 4; p++) wv[p] = *(const u64*)&ws[i * HS + hg * 2 + 32 * p];
#pragma unroll
        for (int r = 0; r < 4; r++)
#pragma unroll
            for (int p = 0; p < 4; p++) acc[r][p] = fma2(xa[r], wv[p], acc[r][p]);
    }
}

// ---------------------------------------------------------------------------
// K1: chunk sums. grid (NBT*NSL, NC), 256 threads. S kept in registers.
// ---------------------------------------------------------------------------
__global__ void __launch_bounds__(256) k_sums(const float* __restrict__ inp,
                                              const float* __restrict__ zz,
                                              const float* __restrict__ W)
{
    extern __shared__ __align__(16) float smem[];
    float* ws = smem;               // [35][128]
    float* xs = smem + Isz * HS;    // [64][37]
    const int tid = threadIdx.x;
    const int b0  = (blockIdx.x / NSL) * BT;
    const int h0  = (blockIdx.x % NSL) * HS;
    const int k   = blockIdx.y;
    const int bg  = tid >> 4, hg = tid & 15;

    u64 acc[4][4];
#pragma unroll
    for (int r = 0; r < 4; r++)
#pragma unroll
        for (int p = 0; p < 4; p++) acc[r][p] = 0ull;

    for (int t = 0; t < LC; t++) {
        const int l = k * LC + t;
        __syncthreads();
        stage_w(ws, W, l, h0, tid);
        stage_x(xs, inp, zz, l, b0, tid);
        __syncthreads();
        encode_step(acc, ws, xs, bg, hg);
    }

    float* sb = g_S + (size_t)k * BH + (size_t)b0 * Hsz + h0;
#pragma unroll
    for (int r = 0; r < 4; r++)
#pragma unroll
        for (int p = 0; p < 4; p++)
            *(u64*)&sb[(size_t)(bg * 4 + r) * Hsz + hg * 2 + 32 * p] = acc[r][p];
}

// ---------------------------------------------------------------------------
// K2: scan chunk sums. P[k] = b_enc + sum_{j<k} S[j].
// ---------------------------------------------------------------------------
__global__ void k_scan(const float* __restrict__ benc)
{
    const int idx = blockIdx.x * 256 + threadIdx.x;
    float run = benc[idx & (Hsz - 1)];
#pragma unroll 5
    for (int k = 0; k < NC; k++) {
        g_P[(size_t)k * BH + idx] = run;
        run += g_S[(size_t)k * BH + idx];
    }
}

// ---------------------------------------------------------------------------
// K3: fused encode + prefix + decode. grid (NBT*NSL, NC), 256 threads.
// Encoder: bg(16) x hg(16), tile 4b x 8h, running a in registers.
// Decoder: bd(16) x jq(4) x kr(4), tile 4b x 10j, h split 4-way with
// kr-skewed iteration (bank spread); kr partials shfl-reduced.
// ---------------------------------------------------------------------------
__global__ void __launch_bounds__(256, 2) k_all(const float* __restrict__ inp,
                                                const float* __restrict__ zz,
                                                const float* __restrict__ W,
                                                const float* __restrict__ Vmu,
                                                const float* __restrict__ Vsg,
                                                const float* __restrict__ Vpi)
{
    extern __shared__ __align__(16) float smem[];
    float* ws = smem;                    // [35][128]   17.5 KB
    float* vs = ws + Isz * HS;           // [128][40]   20 KB
    float* hs = vs + HS * 40;            // [64][130]   33.3 KB
    float* xs = hs + BT * HP;            // [64][37]     9.5 KB
    const int tid = threadIdx.x;
    const int b0  = (blockIdx.x / NSL) * BT;
    const int s   = blockIdx.x % NSL;
    const int h0  = s * HS;
    const int k   = blockIdx.y;
    const int bg  = tid >> 4, hg = tid & 15;          // encode mapping
    const int bd  = tid >> 4, jq = (tid >> 2) & 3, kr = tid & 3;  // decode mapping

    // precompute V staging descriptors (invariant over t): tag<<30 | in-l offset
    unsigned vq[20];
#pragma unroll
    for (int q = 0; q < 20; q++) {
        int u = tid + 256 * q;
        int h = u / 40, jc = u % 40;
        unsigned tag, off;
        if (jc < 15)      { tag = 0u; off = (h0 + h) * Osz + jc; }
        else if (jc < 30) { tag = 1u; off = (h0 + h) * Osz + (jc - 15); }
        else if (jc < 35) { tag = 2u; off = (h0 + h) * Msz + (jc - 30); }
        else              { tag = 3u; off = 0; }
        vq[q] = (tag << 30) | off;
    }

    // init a from carry P (registers), publish relu(a[l0]) to hs
    u64 acc[4][4];
    {
        const float* P = g_P + (size_t)k * BH + (size_t)b0 * Hsz + h0;
#pragma unroll
        for (int r = 0; r < 4; r++)
#pragma unroll
            for (int p = 0; p < 4; p++) {
                float2 v = *(const float2*)&P[(size_t)(bg * 4 + r) * Hsz + hg * 2 + 32 * p];
                acc[r][p] = *(const u64*)&v;
                *(float2*)&hs[(bg * 4 + r) * HP + hg * 2 + 32 * p] =
                    make_float2(fmaxf(v.x, 0.0f), fmaxf(v.y, 0.0f));
            }
    }

    for (int t = 0; t < LC; t++) {
        const int l = k * LC + t;
        // ---- stage W slice, V slice, x tile (hs untouched here)
        stage_w(ws, W, l, h0, tid);
        {
            const size_t lmu = (size_t)l * (Hsz * Osz);
            const size_t lpi = (size_t)l * (Hsz * Msz);
#pragma unroll
            for (int q = 0; q < 20; q++) {
                unsigned tag = vq[q] >> 30, off = vq[q] & 0x3FFFFFFFu;
                float v = 0.0f;
                if (tag == 0u)      v = Vmu[lmu + off];
                else if (tag == 1u) v = Vsg[lmu + off];
                else if (tag == 2u) v = Vpi[lpi + off];
                vs[tid + 256 * q] = v;
            }
        }
        stage_x(xs, inp, zz, l, b0, tid);
        __syncthreads();   // staging done AND prev publish visible

        // ---- decode: o[4b][10j] = relu(a[l]) @ V[l] over this thread's 32 h
        u64 o2[4][5];
#pragma unroll
        for (int r = 0; r < 4; r++)
#pragma unroll
            for (int u = 0; u < 5; u++) o2[r][u] = 0ull;

        const int kr32 = kr * 32;
#pragma unroll 8
        for (int hp = 0; hp < 32; hp++) {
            const int hh = kr32 + ((hp + kr) & 31);   // kr-skew: bank spread
            u64 hv[4];
#pragma unroll
            for (int r = 0; r < 4; r++) hv[r] = splat2(hs[(bd * 4 + r) * HP + hh]);
            const float* vrow = vs + hh * 40 + jq * 10;
#pragma unroll
            for (int u = 0; u < 5; u++) {
                u64 v2 = *(const u64*)&vrow[2 * u];
#pragma unroll
                for (int r = 0; r < 4; r++) o2[r][u] = fma2(hv[r], v2, o2[r][u]);
            }
        }

        // shfl-butterfly over kr (lanes tid^1, tid^2), then lane kr keeps row r=kr
#pragma unroll
        for (int r = 0; r < 4; r++)
#pragma unroll
            for (int u = 0; u < 5; u++) {
                float2 v = *(float2*)&o2[r][u];
                v.x += __shfl_xor_sync(0xFFFFFFFFu, v.x, 1);
                v.x += __shfl_xor_sync(0xFFFFFFFFu, v.x, 2);
                v.y += __shfl_xor_sync(0xFFFFFFFFu, v.y, 1);
                v.y += __shfl_xor_sync(0xFFFFFFFFu, v.y, 2);
                o2[r][u] = *(u64*)&v;
            }
        {
            float* dst = g_part + ((size_t)s * BL + (size_t)l * Bsz + (b0 + bd * 4 + kr)) * 40
                         + jq * 10;
#pragma unroll
            for (int u = 0; u < 5; u++) {
                u64 v = (kr == 0) ? o2[0][u] : (kr == 1) ? o2[1][u]
                       : (kr == 2) ? o2[2][u] : o2[3][u];
                *(u64*)&dst[2 * u] = v;
            }
        }

        // ---- encode: a += x[l] @ W[l]
        encode_step(acc, ws, xs, bg, hg);

        __syncthreads();   // decode reads of hs complete
        // publish relu(a[l+1])
#pragma unroll
        for (int r = 0; r < 4; r++)
#pragma unroll
            for (int p = 0; p < 4; p++) {
                float2 v = *(float2*)&acc[r][p];
                *(float2*)&hs[(bg * 4 + r) * HP + hg * 2 + 32 * p] =
                    make_float2(fmaxf(v.x, 0.0f), fmaxf(v.y, 0.0f));
            }
    }
}

// ---------------------------------------------------------------------------
// K4: reduce slices + output biases. g_part layout [s][l*B + b][40].
// ---------------------------------------------------------------------------
__global__ void __launch_bounds__(280) k_reduce(const float* __restrict__ bmu,
                                                const float* __restrict__ bsg,
                                                const float* __restrict__ bpi,
                                                float* __restrict__ out)
{
    const int p = threadIdx.x / 35;
    const int j = threadIdx.x % 35;
    const size_t pr = (size_t)blockIdx.x * 8 + p;   // = l*256 + b
    const int l = (int)(pr >> 8);
    const int b = (int)(pr & 255);

    float v = 0.0f;
#pragma unroll
    for (int s = 0; s < NSL; s++)
        v += g_part[((size_t)s * BL + pr) * 40 + j];

    float bias;
    if (j < 15)      bias = bmu[l * Osz + j];
    else if (j < 30) bias = bsg[l * Osz + (j - 15)];
    else             bias = bpi[l * Msz + (j - 30)];

    out[((size_t)b * Lsz + l) * Jsz + j] = v + bias;
}

// ---------------------------------------------------------------------------
extern "C" void kernel_launch(void* const* d_in, const int* in_sizes, int n_in,
                              void* d_out, int out_size)
{
    const float* inp  = (const float*)d_in[0];
    const float* zz   = (const float*)d_in[1];
    const float* W    = (const float*)d_in[2];
    const float* benc = (const float*)d_in[3];
    const float* Vmu  = (const float*)d_in[4];
    const float* bmu  = (const float*)d_in[5];
    const float* Vsg  = (const float*)d_in[6];
    const float* bsg  = (const float*)d_in[7];
    const float* Vpi  = (const float*)d_in[8];
    const float* bpi  = (const float*)d_in[9];
    float* out = (float*)d_out;

    const int sm1 = (Isz * HS + BT * XP) * (int)sizeof(float);                        // 27392
    const int sm3 = (Isz * HS + HS * 40 + BT * HP + BT * XP) * (int)sizeof(float);    // 81152
    cudaFuncSetAttribute(k_sums, cudaFuncAttributeMaxDynamicSharedMemorySize, sm1);
    cudaFuncSetAttribute(k_all,  cudaFuncAttributeMaxDynamicSharedMemorySize, sm3);

    k_sums<<<dim3(NBT * NSL, NC), 256, sm1>>>(inp, zz, W);
    k_scan<<<BH / 256, 256>>>(benc);
    k_all <<<dim3(NBT * NSL, NC), 256, sm3>>>(inp, zz, W, Vmu, Vsg, Vpi);
    k_reduce<<<BL / 8, 280>>>(bmu, bsg, bpi, out);
}

// round 6
// speedup vs baseline: 2.8171x; 1.5336x over previous
#include <cuda_runtime.h>
#include <cstdint>

#define Bsz 256
#define Lsz 500
#define Dsz 3
#define Csz 32
#define Isz 35
#define Hsz 512
#define Msz 5
#define Osz 15
#define Jsz 35
#define NC  50
#define LC  10
#define BH  (Bsz*Hsz)   /* 131072 */
#define BL  (Bsz*Lsz)   /* 128000 */
#define NSL 4           /* h slices */
#define HS  (Hsz/NSL)   /* 128 */
#define BT  128         /* b tile */
#define NBT (Bsz/BT)    /* 2 */
#define HP  130         /* hs row stride */
#define XP  44          /* xs row stride (16B-alignable, bank-spread) */
#define NT  512

// smem float counts (per buffer)
#define WCNT (Isz*HS)   /* 4480 */
#define VCNT (HS*40)    /* 5120 */
#define XCNT (BT*XP)    /* 5632 */
#define HCNT (BT*HP)    /* 16640 */

// Scratch (device globals are allowed)
__device__ __align__(16) float g_S[(size_t)NC * BH];           // chunk sums      26 MB
__device__ __align__(16) float g_P[(size_t)NC * BH];           // chunk carries   26 MB
__device__ __align__(16) float g_part[(size_t)NSL * BL * 40];  // decode partials 82 MB

using u64 = unsigned long long;

__device__ __forceinline__ u64 splat2(float x) {
    u64 r; unsigned u = __float_as_uint(x);
    asm("mov.b64 %0, {%1, %1};" : "=l"(r) : "r"(u));
    return r;
}
__device__ __forceinline__ u64 fma2(u64 a, u64 b, u64 c) {
    u64 d; asm("fma.rn.f32x2 %0, %1, %2, %3;" : "=l"(d) : "l"(a), "l"(b), "l"(c));
    return d;
}
__device__ __forceinline__ void cp16(unsigned dst, const void* src) {
    asm volatile("cp.async.ca.shared.global [%0], [%1], 16;" :: "r"(dst), "l"(src));
}
__device__ __forceinline__ void cp4(unsigned dst, const void* src) {
    asm volatile("cp.async.ca.shared.global [%0], [%1], 4;" :: "r"(dst), "l"(src));
}
__device__ __forceinline__ void cp_commit() { asm volatile("cp.async.commit_group;"); }
__device__ __forceinline__ void cp_wait0()  { asm volatile("cp.async.wait_group 0;"); }

// ---------------------------------------------------------------------------
// Async staging of W slice + x tile for step l into buffer (u32 smem addrs).
// ---------------------------------------------------------------------------
__device__ __forceinline__ void stage_wx_async(unsigned ws_a, unsigned xs_a,
                                               const float* __restrict__ W,
                                               const float* __restrict__ inp,
                                               const float* __restrict__ zz,
                                               int l, int h0, int b0, int tid)
{
    // W slice: 1120 float4
    const float4* wsrc = (const float4*)(W + (size_t)l * (Isz * Hsz)) + (h0 >> 2);
#pragma unroll
    for (int q = 0; q < 3; q++) {
        int idx = tid + NT * q;
        if (idx < Isz * 32) {
            int row = idx >> 5, col = idx & 31;
            cp16(ws_a + (unsigned)(row * 32 + col) * 16, wsrc + row * 128 + col);
        }
    }
    // z part: 1024 float4 -> xs cols 4..35 (as floats 3..34 shifted to 4..35)
#pragma unroll
    for (int q = 0; q < 2; q++) {
        int idx = tid + NT * q;
        int b = idx >> 3, qf = idx & 7;
        cp16(xs_a + (unsigned)(b * XP + 4 + qf * 4) * 4,
             zz + (size_t)(b0 + b) * (Lsz * Csz) + (size_t)l * Csz + qf * 4);
    }
    // inp part: 384 scalars -> xs cols 0..2
    if (tid < BT * Dsz) {
        int b = tid / Dsz, i = tid % Dsz;
        cp4(xs_a + (unsigned)(b * XP + i) * 4,
            inp + (size_t)(b0 + b) * (Lsz * Dsz) + (size_t)l * Dsz + i);
    }
}

// Encoder micro-kernel: acc[4b][4 u64 = 8h] += x @ Wslice.
// bg = tid>>4 (0..31), hg = tid&15. x layout: inp at cols 0..2, z at cols 4..35.
__device__ __forceinline__ void encode_step(u64 acc[4][4], const float* ws,
                                            const float* xs, int bg, int hg)
{
#pragma unroll
    for (int i = 0; i < Isz; i++) {
        const int xc = (i < Dsz) ? i : i + 1;   // compile-time: skip pad col 3
        u64 xa[4], wv[4];
#pragma unroll
        for (int r = 0; r < 4; r++) xa[r] = splat2(xs[(bg * 4 + r) * XP + xc]);
#pragma unroll
        for (int p = 0; p < 4; p++) wv[p] = *(const u64*)&ws[i * HS + hg * 2 + 32 * p];
#pragma unroll
        for (int r = 0; r < 4; r++)
#pragma unroll
            for (int p = 0; p < 4; p++) acc[r][p] = fma2(xa[r], wv[p], acc[r][p]);
    }
}

// ---------------------------------------------------------------------------
// K1: chunk sums. grid (NBT*NSL, NC), 512 threads, double-buffered staging.
// ---------------------------------------------------------------------------
__global__ void __launch_bounds__(NT) k_sums(const float* __restrict__ inp,
                                             const float* __restrict__ zz,
                                             const float* __restrict__ W)
{
    extern __shared__ __align__(16) float smem[];
    float* ws[2] = { smem, smem + WCNT };
    float* xs[2] = { smem + 2 * WCNT, smem + 2 * WCNT + XCNT };
    const unsigned sbase = (unsigned)__cvta_generic_to_shared(smem);
    const unsigned ws_a[2] = { sbase, sbase + WCNT * 4u };
    const unsigned xs_a[2] = { sbase + 2u * WCNT * 4u, sbase + (2u * WCNT + XCNT) * 4u };

    const int tid = threadIdx.x;
    const int b0  = (blockIdx.x / NSL) * BT;
    const int h0  = (blockIdx.x % NSL) * HS;
    const int k   = blockIdx.y;
    const int bg  = tid >> 4, hg = tid & 15;

    u64 acc[4][4];
#pragma unroll
    for (int r = 0; r < 4; r++)
#pragma unroll
        for (int p = 0; p < 4; p++) acc[r][p] = 0ull;

    stage_wx_async(ws_a[0], xs_a[0], W, inp, zz, k * LC, h0, b0, tid);
    cp_commit(); cp_wait0();
    __syncthreads();

    for (int t = 0; t < LC; t++) {
        const int cur = t & 1, nxt = cur ^ 1;
        if (t + 1 < LC) {
            stage_wx_async(ws_a[nxt], xs_a[nxt], W, inp, zz, k * LC + t + 1, h0, b0, tid);
            cp_commit();
        }
        encode_step(acc, ws[cur], xs[cur], bg, hg);
        cp_wait0();
        __syncthreads();
    }

    float* sb = g_S + (size_t)k * BH + (size_t)b0 * Hsz + h0;
#pragma unroll
    for (int r = 0; r < 4; r++)
#pragma unroll
        for (int p = 0; p < 4; p++)
            *(u64*)&sb[(size_t)(bg * 4 + r) * Hsz + hg * 2 + 32 * p] = acc[r][p];
}

// ---------------------------------------------------------------------------
// K2: scan chunk sums. P[k] = b_enc + sum_{j<k} S[j].
// ---------------------------------------------------------------------------
__global__ void k_scan(const float* __restrict__ benc)
{
    const int idx = blockIdx.x * 256 + threadIdx.x;
    float run = benc[idx & (Hsz - 1)];
#pragma unroll 5
    for (int k = 0; k < NC; k++) {
        g_P[(size_t)k * BH + idx] = run;
        run += g_S[(size_t)k * BH + idx];
    }
}

// ---------------------------------------------------------------------------
// K3: fused encode+prefix+decode, pipelined. grid (NBT*NSL, NC), 512 threads.
// Encoder: bg(32) x hg(16), 4b x 8h, running a in registers.
// Decoder: bd(32) x jq(4) x kr(4), 4b x 10j, h split 4-way, kr-skewed.
// W/x double-buffered via cp.async; V double-buffered via LDG->regs->STS.
// ---------------------------------------------------------------------------
__global__ void __launch_bounds__(NT) k_all(const float* __restrict__ inp,
                                            const float* __restrict__ zz,
                                            const float* __restrict__ W,
                                            const float* __restrict__ Vmu,
                                            const float* __restrict__ Vsg,
                                            const float* __restrict__ Vpi)
{
    extern __shared__ __align__(16) float smem[];
    float* ws[2] = { smem, smem + WCNT };
    float* vs[2] = { smem + 2 * WCNT, smem + 2 * WCNT + VCNT };
    float* hs    = smem + 2 * WCNT + 2 * VCNT;
    float* xs[2] = { hs + HCNT, hs + HCNT + XCNT };
    const unsigned sbase = (unsigned)__cvta_generic_to_shared(smem);
    const unsigned ws_a[2] = { sbase, sbase + WCNT * 4u };
    const unsigned xs_a[2] = { sbase + (2u * WCNT + 2u * VCNT + HCNT) * 4u,
                               sbase + (2u * WCNT + 2u * VCNT + HCNT + XCNT) * 4u };

    const int tid = threadIdx.x;
    const int b0  = (blockIdx.x / NSL) * BT;
    const int s   = blockIdx.x % NSL;
    const int h0  = s * HS;
    const int k   = blockIdx.y;
    const int bg  = tid >> 4, hg = tid & 15;                       // encode
    const int bd  = tid >> 4, jq = (tid >> 2) & 3, kr = tid & 3;   // decode

    // V staging descriptors (10 per thread): tag<<30 | in-l offset
    unsigned vq[10];
#pragma unroll
    for (int q = 0; q < 10; q++) {
        int u = tid + NT * q;
        int h = u / 40, jc = u % 40;
        unsigned tag, off;
        if (jc < 15)      { tag = 0u; off = (h0 + h) * Osz + jc; }
        else if (jc < 30) { tag = 1u; off = (h0 + h) * Osz + (jc - 15); }
        else if (jc < 35) { tag = 2u; off = (h0 + h) * Msz + (jc - 30); }
        else              { tag = 3u; off = 0; }
        vq[q] = (tag << 30) | off;
    }

    // preload step 0: W/x async; V via regs
    stage_wx_async(ws_a[0], xs_a[0], W, inp, zz, k * LC, h0, b0, tid);
    cp_commit();
    {
        const size_t lmu = (size_t)(k * LC) * (Hsz * Osz);
        const size_t lpi = (size_t)(k * LC) * (Hsz * Msz);
#pragma unroll
        for (int q = 0; q < 10; q++) {
            unsigned tag = vq[q] >> 30, off = vq[q] & 0x3FFFFFFFu;
            float v = 0.0f;
            if (tag == 0u)      v = Vmu[lmu + off];
            else if (tag == 1u) v = Vsg[lmu + off];
            else if (tag == 2u) v = Vpi[lpi + off];
            vs[0][tid + NT * q] = v;
        }
    }

    // init a from carry P (registers), publish relu(a[l0]) to hs
    u64 acc[4][4];
    {
        const float* P = g_P + (size_t)k * BH + (size_t)b0 * Hsz + h0;
#pragma unroll
        for (int r = 0; r < 4; r++)
#pragma unroll
            for (int p = 0; p < 4; p++) {
                float2 v = *(const float2*)&P[(size_t)(bg * 4 + r) * Hsz + hg * 2 + 32 * p];
                acc[r][p] = *(const u64*)&v;
                *(float2*)&hs[(bg * 4 + r) * HP + hg * 2 + 32 * p] =
                    make_float2(fmaxf(v.x, 0.0f), fmaxf(v.y, 0.0f));
            }
    }
    cp_wait0();
    __syncthreads();

    for (int t = 0; t < LC; t++) {
        const int l = k * LC + t;
        const int cur = t & 1, nxt = cur ^ 1;

        // ---- issue next-step staging first (latency overlaps compute)
        float vreg[10];
        if (t + 1 < LC) {
            stage_wx_async(ws_a[nxt], xs_a[nxt], W, inp, zz, l + 1, h0, b0, tid);
            cp_commit();
            const size_t lmu = (size_t)(l + 1) * (Hsz * Osz);
            const size_t lpi = (size_t)(l + 1) * (Hsz * Msz);
#pragma unroll
            for (int q = 0; q < 10; q++) {
                unsigned tag = vq[q] >> 30, off = vq[q] & 0x3FFFFFFFu;
                float v = 0.0f;
                if (tag == 0u)      v = Vmu[lmu + off];
                else if (tag == 1u) v = Vsg[lmu + off];
                else if (tag == 2u) v = Vpi[lpi + off];
                vreg[q] = v;
            }
        }

        // ---- decode: o[4b][10j] = relu(a[l]) @ V[l] over this thread's 32 h
        u64 o2[4][5];
#pragma unroll
        for (int r = 0; r < 4; r++)
#pragma unroll
            for (int u = 0; u < 5; u++) o2[r][u] = 0ull;

        const float* vcur = vs[cur];
        const int kr32 = kr * 32;
#pragma unroll 8
        for (int hp = 0; hp < 32; hp++) {
            const int hh = kr32 + ((hp + kr) & 31);   // kr-skew: bank spread
            u64 hv[4];
#pragma unroll
            for (int r = 0; r < 4; r++) hv[r] = splat2(hs[(bd * 4 + r) * HP + hh]);
            const float* vrow = vcur + hh * 40 + jq * 10;
#pragma unroll
            for (int u = 0; u < 5; u++) {
                u64 v2 = *(const u64*)&vrow[2 * u];
#pragma unroll
                for (int r = 0; r < 4; r++) o2[r][u] = fma2(hv[r], v2, o2[r][u]);
            }
        }

        // shfl-butterfly over kr; lane kr keeps row r=kr; coalesced store
#pragma unroll
        for (int r = 0; r < 4; r++)
#pragma unroll
            for (int u = 0; u < 5; u++) {
                float2 v = *(float2*)&o2[r][u];
                v.x += __shfl_xor_sync(0xFFFFFFFFu, v.x, 1);
                v.x += __shfl_xor_sync(0xFFFFFFFFu, v.x, 2);
                v.y += __shfl_xor_sync(0xFFFFFFFFu, v.y, 1);
                v.y += __shfl_xor_sync(0xFFFFFFFFu, v.y, 2);
                o2[r][u] = *(u64*)&v;
            }
        {
            float* dst = g_part + ((size_t)s * BL + (size_t)l * Bsz + (b0 + bd * 4 + kr)) * 40
                         + jq * 10;
#pragma unroll
            for (int u = 0; u < 5; u++) {
                u64 v = (kr == 0) ? o2[0][u] : (kr == 1) ? o2[1][u]
                       : (kr == 2) ? o2[2][u] : o2[3][u];
                *(u64*)&dst[2 * u] = v;
            }
        }

        // ---- encode: a += x[l] @ W[l]
        encode_step(acc, ws[cur], xs[cur], bg, hg);

        __syncthreads();   // all decode reads of hs complete
        // publish relu(a[l+1]); store next V; drain cp.async
#pragma unroll
        for (int r = 0; r < 4; r++)
#pragma unroll
            for (int p = 0; p < 4; p++) {
                float2 v = *(float2*)&acc[r][p];
                *(float2*)&hs[(bg * 4 + r) * HP + hg * 2 + 32 * p] =
                    make_float2(fmaxf(v.x, 0.0f), fmaxf(v.y, 0.0f));
            }
        if (t + 1 < LC) {
            float* vn = vs[nxt];
#pragma unroll
            for (int q = 0; q < 10; q++) vn[tid + NT * q] = vreg[q];
            cp_wait0();
        }
        __syncthreads();
    }
}

// ---------------------------------------------------------------------------
// K4: reduce slices + output biases. g_part layout [s][l*B + b][40].
// ---------------------------------------------------------------------------
__global__ void __launch_bounds__(280) k_reduce(const float* __restrict__ bmu,
                                                const float* __restrict__ bsg,
                                                const float* __restrict__ bpi,
                                                float* __restrict__ out)
{
    const int p = threadIdx.x / 35;
    const int j = threadIdx.x % 35;
    const size_t pr = (size_t)blockIdx.x * 8 + p;   // = l*256 + b
    const int l = (int)(pr >> 8);
    const int b = (int)(pr & 255);

    float v = 0.0f;
#pragma unroll
    for (int s = 0; s < NSL; s++)
        v += g_part[((size_t)s * BL + pr) * 40 + j];

    float bias;
    if (j < 15)      bias = bmu[l * Osz + j];
    else if (j < 30) bias = bsg[l * Osz + (j - 15)];
    else             bias = bpi[l * Msz + (j - 30)];

    out[((size_t)b * Lsz + l) * Jsz + j] = v + bias;
}

// ---------------------------------------------------------------------------
extern "C" void kernel_launch(void* const* d_in, const int* in_sizes, int n_in,
                              void* d_out, int out_size)
{
    const float* inp  = (const float*)d_in[0];
    const float* zz   = (const float*)d_in[1];
    const float* W    = (const float*)d_in[2];
    const float* benc = (const float*)d_in[3];
    const float* Vmu  = (const float*)d_in[4];
    const float* bmu  = (const float*)d_in[5];
    const float* Vsg  = (const float*)d_in[6];
    const float* bsg  = (const float*)d_in[7];
    const float* Vpi  = (const float*)d_in[8];
    const float* bpi  = (const float*)d_in[9];
    float* out = (float*)d_out;

    const int sm1 = (2 * WCNT + 2 * XCNT) * (int)sizeof(float);                    // 80.9 KB
    const int sm3 = (2 * WCNT + 2 * VCNT + HCNT + 2 * XCNT) * (int)sizeof(float);  // 188.4 KB
    cudaFuncSetAttribute(k_sums, cudaFuncAttributeMaxDynamicSharedMemorySize, sm1);
    cudaFuncSetAttribute(k_all,  cudaFuncAttributeMaxDynamicSharedMemorySize, sm3);

    k_sums<<<dim3(NBT * NSL, NC), NT, sm1>>>(inp, zz, W);
    k_scan<<<BH / 256, 256>>>(benc);
    k_all <<<dim3(NBT * NSL, NC), NT, sm3>>>(inp, zz, W, Vmu, Vsg, Vpi);
    k_reduce<<<BL / 8, 280>>>(bmu, bsg, bpi, out);
}

// round 7
// speedup vs baseline: 2.9616x; 1.0513x over previous
#include <cuda_runtime.h>
#include <cuda_fp16.h>
#include <cstdint>

#define Bsz 256
#define Lsz 500
#define Dsz 3
#define Csz 32
#define Isz 35
#define Hsz 512
#define Msz 5
#define Osz 15
#define Jsz 35
#define NC  50
#define LC  10
#define BH  (Bsz*Hsz)   /* 131072 */
#define BL  (Bsz*Lsz)   /* 128000 */
#define NSL 4           /* h slices */
#define HS  (Hsz/NSL)   /* 128 */
#define BT  128         /* b tile */
#define NBT (Bsz/BT)    /* 2 */
#define HP  130         /* hs row stride (floats) */
#define XP  44          /* xs row stride (floats) */
#define NT  512
#define CP  136         /* c16 smem row stride (halfs) -> 272B, bank-spread */

// smem float counts
#define WCNT (Isz*HS)   /* 4480 */
#define VCNT (HS*40)    /* 5120 */
#define XCNT (BT*XP)    /* 5632 */
#define HCNT (BT*HP)    /* 16640 */
#define CCNT (BT*CP/2)  /* 8704 floats per c16 buffer */

// Scratch (device globals are allowed)
__device__ __align__(16) float  g_S[(size_t)NC * BH];           // chunk sums    26 MB
__device__ __align__(16) float  g_P[(size_t)NC * BH];           // chunk carries 26 MB
__device__ __align__(16) float  g_part[(size_t)NSL * BL * 40];  // partials      82 MB
__device__ __align__(16) __half g_c16[(size_t)Lsz * BH];        // c in fp16    131 MB

using u64 = unsigned long long;

__device__ __forceinline__ u64 splat2(float x) {
    u64 r; unsigned u = __float_as_uint(x);
    asm("mov.b64 %0, {%1, %1};" : "=l"(r) : "r"(u));
    return r;
}
__device__ __forceinline__ u64 fma2(u64 a, u64 b, u64 c) {
    u64 d; asm("fma.rn.f32x2 %0, %1, %2, %3;" : "=l"(d) : "l"(a), "l"(b), "l"(c));
    return d;
}
__device__ __forceinline__ u64 add2(u64 a, u64 b) {
    u64 d; asm("add.rn.f32x2 %0, %1, %2;" : "=l"(d) : "l"(a), "l"(b));
    return d;
}
__device__ __forceinline__ void cp16(unsigned dst, const void* src) {
    asm volatile("cp.async.ca.shared.global [%0], [%1], 16;" :: "r"(dst), "l"(src));
}
__device__ __forceinline__ void cp4(unsigned dst, const void* src) {
    asm volatile("cp.async.ca.shared.global [%0], [%1], 4;" :: "r"(dst), "l"(src));
}
__device__ __forceinline__ void cp_commit() { asm volatile("cp.async.commit_group;"); }
__device__ __forceinline__ void cp_wait0()  { asm volatile("cp.async.wait_group 0;"); }

// ---------------------------------------------------------------------------
// Async staging of W slice + x tile (k_sums only).
// ---------------------------------------------------------------------------
__device__ __forceinline__ void stage_wx_async(unsigned ws_a, unsigned xs_a,
                                               const float* __restrict__ W,
                                               const float* __restrict__ inp,
                                               const float* __restrict__ zz,
                                               int l, int h0, int b0, int tid)
{
    const float4* wsrc = (const float4*)(W + (size_t)l * (Isz * Hsz)) + (h0 >> 2);
#pragma unroll
    for (int q = 0; q < 3; q++) {
        int idx = tid + NT * q;
        if (idx < Isz * 32) {
            int row = idx >> 5, col = idx & 31;
            cp16(ws_a + (unsigned)(row * 32 + col) * 16, wsrc + row * 128 + col);
        }
    }
#pragma unroll
    for (int q = 0; q < 2; q++) {
        int idx = tid + NT * q;
        int b = idx >> 3, qf = idx & 7;
        cp16(xs_a + (unsigned)(b * XP + 4 + qf * 4) * 4,
             zz + (size_t)(b0 + b) * (Lsz * Csz) + (size_t)l * Csz + qf * 4);
    }
    if (tid < BT * Dsz) {
        int b = tid / Dsz, i = tid % Dsz;
        cp4(xs_a + (unsigned)(b * XP + i) * 4,
            inp + (size_t)(b0 + b) * (Lsz * Dsz) + (size_t)l * Dsz + i);
    }
}

// Encoder micro-kernel: c[4b][4 u64 = 8h] = x @ Wslice (fresh accumulators).
__device__ __forceinline__ void encode_step(u64 c2[4][4], const float* ws,
                                            const float* xs, int bg, int hg)
{
#pragma unroll
    for (int r = 0; r < 4; r++)
#pragma unroll
        for (int p = 0; p < 4; p++) c2[r][p] = 0ull;
#pragma unroll
    for (int i = 0; i < Isz; i++) {
        const int xc = (i < Dsz) ? i : i + 1;
        u64 xa[4], wv[4];
#pragma unroll
        for (int r = 0; r < 4; r++) xa[r] = splat2(xs[(bg * 4 + r) * XP + xc]);
#pragma unroll
        for (int p = 0; p < 4; p++) wv[p] = *(const u64*)&ws[i * HS + hg * 2 + 32 * p];
#pragma unroll
        for (int r = 0; r < 4; r++)
#pragma unroll
            for (int p = 0; p < 4; p++) c2[r][p] = fma2(xa[r], wv[p], c2[r][p]);
    }
}

// ---------------------------------------------------------------------------
// K1: THE encoder (runs once). Computes c[l], stores fp16 copy to g_c16,
// keeps fp32 chunk sum S in registers. grid (NBT*NSL, NC), 512 threads.
// ---------------------------------------------------------------------------
__global__ void __launch_bounds__(NT) k_sums(const float* __restrict__ inp,
                                             const float* __restrict__ zz,
                                             const float* __restrict__ W)
{
    extern __shared__ __align__(16) float smem[];
    float* ws[2] = { smem, smem + WCNT };
    float* xs[2] = { smem + 2 * WCNT, smem + 2 * WCNT + XCNT };
    const unsigned sbase = (unsigned)__cvta_generic_to_shared(smem);
    const unsigned ws_a[2] = { sbase, sbase + WCNT * 4u };
    const unsigned xs_a[2] = { sbase + 2u * WCNT * 4u, sbase + (2u * WCNT + XCNT) * 4u };

    const int tid = threadIdx.x;
    const int b0  = (blockIdx.x / NSL) * BT;
    const int h0  = (blockIdx.x % NSL) * HS;
    const int k   = blockIdx.y;
    const int bg  = tid >> 4, hg = tid & 15;

    u64 acc[4][4];
#pragma unroll
    for (int r = 0; r < 4; r++)
#pragma unroll
        for (int p = 0; p < 4; p++) acc[r][p] = 0ull;

    stage_wx_async(ws_a[0], xs_a[0], W, inp, zz, k * LC, h0, b0, tid);
    cp_commit(); cp_wait0();
    __syncthreads();

    for (int t = 0; t < LC; t++) {
        const int l = k * LC + t;
        const int cur = t & 1, nxt = cur ^ 1;
        if (t + 1 < LC) {
            stage_wx_async(ws_a[nxt], xs_a[nxt], W, inp, zz, l + 1, h0, b0, tid);
            cp_commit();
        }
        u64 c2[4][4];
        encode_step(c2, ws[cur], xs[cur], bg, hg);
        // accumulate S (fp32) and store fp16 copy of c[l]
#pragma unroll
        for (int r = 0; r < 4; r++) {
            __half* crow = g_c16 + ((size_t)l * Bsz + b0 + bg * 4 + r) * Hsz + h0;
#pragma unroll
            for (int p = 0; p < 4; p++) {
                acc[r][p] = add2(acc[r][p], c2[r][p]);
                float2 f = *(float2*)&c2[r][p];
                *(__half2*)&crow[hg * 2 + 32 * p] = __floats2half2_rn(f.x, f.y);
            }
        }
        cp_wait0();
        __syncthreads();
    }

    float* sb = g_S + (size_t)k * BH + (size_t)b0 * Hsz + h0;
#pragma unroll
    for (int r = 0; r < 4; r++)
#pragma unroll
        for (int p = 0; p < 4; p++)
            *(u64*)&sb[(size_t)(bg * 4 + r) * Hsz + hg * 2 + 32 * p] = acc[r][p];
}

// ---------------------------------------------------------------------------
// K2: scan chunk sums. P[k] = b_enc + sum_{j<k} S[j].
// ---------------------------------------------------------------------------
__global__ void k_scan(const float* __restrict__ benc)
{
    const int idx = blockIdx.x * 256 + threadIdx.x;
    float run = benc[idx & (Hsz - 1)];
#pragma unroll 5
    for (int k = 0; k < NC; k++) {
        g_P[(size_t)k * BH + idx] = run;
        run += g_S[(size_t)k * BH + idx];
    }
}

// ---------------------------------------------------------------------------
// K3: prefix + decode (no encode). grid (NBT*NSL, NC), 512 threads.
// Running a in registers (thread = 4b x 8h, bg/hg); updated from staged c16.
// Decoder: bd(32) x jq(4) x kr(4), 4b x 10j, kr-skewed h iteration.
// c16 double-buffered via cp.async; V double-buffered via LDG->regs->STS.
// ---------------------------------------------------------------------------
__global__ void __launch_bounds__(NT) k_all(const float* __restrict__ Vmu,
                                            const float* __restrict__ Vsg,
                                            const float* __restrict__ Vpi)
{
    extern __shared__ __align__(16) float smem[];
    float*  vs[2] = { smem, smem + VCNT };
    float*  hs    = smem + 2 * VCNT;
    __half* cs[2] = { (__half*)(hs + HCNT), (__half*)(hs + HCNT) + BT * CP };
    const unsigned sbase = (unsigned)__cvta_generic_to_shared(smem);
    const unsigned cs_a[2] = { sbase + (2u * VCNT + HCNT) * 4u,
                               sbase + (2u * VCNT + HCNT) * 4u + (unsigned)BT * CP * 2u };

    const int tid = threadIdx.x;
    const int b0  = (blockIdx.x / NSL) * BT;
    const int s   = blockIdx.x % NSL;
    const int h0  = s * HS;
    const int k   = blockIdx.y;
    const int bg  = tid >> 4, hg = tid & 15;                       // a-owner map
    const int bd  = tid >> 4, jq = (tid >> 2) & 3, kr = tid & 3;   // decode map

    // V staging descriptors: tag<<30 | in-l offset
    unsigned vq[10];
#pragma unroll
    for (int q = 0; q < 10; q++) {
        int u = tid + NT * q;
        int h = u / 40, jc = u % 40;
        unsigned tag, off;
        if (jc < 15)      { tag = 0u; off = (h0 + h) * Osz + jc; }
        else if (jc < 30) { tag = 1u; off = (h0 + h) * Osz + (jc - 15); }
        else if (jc < 35) { tag = 2u; off = (h0 + h) * Msz + (jc - 30); }
        else              { tag = 3u; off = 0; }
        vq[q] = (tag << 30) | off;
    }

    // stage c16[l0]: 2048 16B-chunks (row = 128 halfs = 16 chunks)
    {
        const int l0 = k * LC;
#pragma unroll
        for (int q = 0; q < 4; q++) {
            int idx = tid + NT * q;
            int row = idx >> 4, ch = idx & 15;
            cp16(cs_a[0] + (unsigned)(row * CP + ch * 8) * 2,
                 g_c16 + ((size_t)l0 * Bsz + b0 + row) * Hsz + h0 + ch * 8);
        }
        cp_commit();
    }
    // stage V[l0] via regs
    {
        const size_t lmu = (size_t)(k * LC) * (Hsz * Osz);
        const size_t lpi = (size_t)(k * LC) * (Hsz * Msz);
#pragma unroll
        for (int q = 0; q < 10; q++) {
            unsigned tag = vq[q] >> 30, off = vq[q] & 0x3FFFFFFFu;
            float v = 0.0f;
            if (tag == 0u)      v = Vmu[lmu + off];
            else if (tag == 1u) v = Vsg[lmu + off];
            else if (tag == 2u) v = Vpi[lpi + off];
            vs[0][tid + NT * q] = v;
        }
    }

    // init a from carry P, publish relu(a[l0])
    u64 acc[4][4];
    {
        const float* P = g_P + (size_t)k * BH + (size_t)b0 * Hsz + h0;
#pragma unroll
        for (int r = 0; r < 4; r++)
#pragma unroll
            for (int p = 0; p < 4; p++) {
                float2 v = *(const float2*)&P[(size_t)(bg * 4 + r) * Hsz + hg * 2 + 32 * p];
                acc[r][p] = *(const u64*)&v;
                *(float2*)&hs[(bg * 4 + r) * HP + hg * 2 + 32 * p] =
                    make_float2(fmaxf(v.x, 0.0f), fmaxf(v.y, 0.0f));
            }
    }
    cp_wait0();
    __syncthreads();

    for (int t = 0; t < LC; t++) {
        const int l = k * LC + t;
        const int cur = t & 1, nxt = cur ^ 1;

        // ---- issue next-step staging (c16[l+1] async, V[l+1] via regs)
        float vreg[10];
        if (t + 1 < LC) {
#pragma unroll
            for (int q = 0; q < 4; q++) {
                int idx = tid + NT * q;
                int row = idx >> 4, ch = idx & 15;
                cp16(cs_a[nxt] + (unsigned)(row * CP + ch * 8) * 2,
                     g_c16 + ((size_t)(l + 1) * Bsz + b0 + row) * Hsz + h0 + ch * 8);
            }
            cp_commit();
            const size_t lmu = (size_t)(l + 1) * (Hsz * Osz);
            const size_t lpi = (size_t)(l + 1) * (Hsz * Msz);
#pragma unroll
            for (int q = 0; q < 10; q++) {
                unsigned tag = vq[q] >> 30, off = vq[q] & 0x3FFFFFFFu;
                float v = 0.0f;
                if (tag == 0u)      v = Vmu[lmu + off];
                else if (tag == 1u) v = Vsg[lmu + off];
                else if (tag == 2u) v = Vpi[lpi + off];
                vreg[q] = v;
            }
        }

        // ---- decode: o[4b][10j] = relu(a[l]) @ V[l] over this thread's 32 h
        u64 o2[4][5];
#pragma unroll
        for (int r = 0; r < 4; r++)
#pragma unroll
            for (int u = 0; u < 5; u++) o2[r][u] = 0ull;

        const float* vcur = vs[cur];
        const int kr32 = kr * 32;
#pragma unroll 8
        for (int hp = 0; hp < 32; hp++) {
            const int hh = kr32 + ((hp + kr) & 31);
            u64 hv[4];
#pragma unroll
            for (int r = 0; r < 4; r++) hv[r] = splat2(hs[(bd * 4 + r) * HP + hh]);
            const float* vrow = vcur + hh * 40 + jq * 10;
#pragma unroll
            for (int u = 0; u < 5; u++) {
                u64 v2 = *(const u64*)&vrow[2 * u];
#pragma unroll
                for (int r = 0; r < 4; r++) o2[r][u] = fma2(hv[r], v2, o2[r][u]);
            }
        }

        // shfl-butterfly over kr; lane kr keeps row r=kr; coalesced store
#pragma unroll
        for (int r = 0; r < 4; r++)
#pragma unroll
            for (int u = 0; u < 5; u++) {
                float2 v = *(float2*)&o2[r][u];
                v.x += __shfl_xor_sync(0xFFFFFFFFu, v.x, 1);
                v.x += __shfl_xor_sync(0xFFFFFFFFu, v.x, 2);
                v.y += __shfl_xor_sync(0xFFFFFFFFu, v.y, 1);
                v.y += __shfl_xor_sync(0xFFFFFFFFu, v.y, 2);
                o2[r][u] = *(u64*)&v;
            }
        {
            float* dst = g_part + ((size_t)s * BL + (size_t)l * Bsz + (b0 + bd * 4 + kr)) * 40
                         + jq * 10;
#pragma unroll
            for (int u = 0; u < 5; u++) {
                u64 v = (kr == 0) ? o2[0][u] : (kr == 1) ? o2[1][u]
                       : (kr == 2) ? o2[2][u] : o2[3][u];
                *(u64*)&dst[2 * u] = v;
            }
        }

        // ---- recurrence: a += c16[l] (register-local; cur buffer resident)
        {
            const __half* cb = cs[cur];
#pragma unroll
            for (int r = 0; r < 4; r++)
#pragma unroll
                for (int p = 0; p < 4; p++) {
                    __half2 h2 = *(const __half2*)&cb[(bg * 4 + r) * CP + hg * 2 + 32 * p];
                    float2 c = __half22float2(h2);
                    float2 a = *(float2*)&acc[r][p];
                    a.x += c.x; a.y += c.y;
                    acc[r][p] = *(u64*)&a;
                }
        }

        __syncthreads();   // all decode reads of hs complete
        // publish relu(a[l+1]); store next V; drain cp.async
#pragma unroll
        for (int r = 0; r < 4; r++)
#pragma unroll
            for (int p = 0; p < 4; p++) {
                float2 v = *(float2*)&acc[r][p];
                *(float2*)&hs[(bg * 4 + r) * HP + hg * 2 + 32 * p] =
                    make_float2(fmaxf(v.x, 0.0f), fmaxf(v.y, 0.0f));
            }
        if (t + 1 < LC) {
            float* vn = vs[nxt];
#pragma unroll
            for (int q = 0; q < 10; q++) vn[tid + NT * q] = vreg[q];
            cp_wait0();
        }
        __syncthreads();
    }
}

// ---------------------------------------------------------------------------
// K4: reduce slices + output biases. g_part layout [s][l*B + b][40].
// ---------------------------------------------------------------------------
__global__ void __launch_bounds__(280) k_reduce(const float* __restrict__ bmu,
                                                const float* __restrict__ bsg,
                                                const float* __restrict__ bpi,
                                                float* __restrict__ out)
{
    const int p = threadIdx.x / 35;
    const int j = threadIdx.x % 35;
    const size_t pr = (size_t)blockIdx.x * 8 + p;   // = l*256 + b
    const int l = (int)(pr >> 8);
    const int b = (int)(pr & 255);

    float v = 0.0f;
#pragma unroll
    for (int s = 0; s < NSL; s++)
        v += g_part[((size_t)s * BL + pr) * 40 + j];

    float bias;
    if (j < 15)      bias = bmu[l * Osz + j];
    else if (j < 30) bias = bsg[l * Osz + (j - 15)];
    else             bias = bpi[l * Msz + (j - 30)];

    out[((size_t)b * Lsz + l) * Jsz + j] = v + bias;
}

// ---------------------------------------------------------------------------
extern "C" void kernel_launch(void* const* d_in, const int* in_sizes, int n_in,
                              void* d_out, int out_size)
{
    const float* inp  = (const float*)d_in[0];
    const float* zz   = (const float*)d_in[1];
    const float* W    = (const float*)d_in[2];
    const float* benc = (const float*)d_in[3];
    const float* Vmu  = (const float*)d_in[4];
    const float* bmu  = (const float*)d_in[5];
    const float* Vsg  = (const float*)d_in[6];
    const float* bsg  = (const float*)d_in[7];
    const float* Vpi  = (const float*)d_in[8];
    const float* bpi  = (const float*)d_in[9];
    float* out = (float*)d_out;

    const int sm1 = (2 * WCNT + 2 * XCNT) * (int)sizeof(float);                 // 80.9 KB
    const int sm3 = (2 * VCNT + HCNT + 2 * CCNT) * (int)sizeof(float);          // 177.2 KB
    cudaFuncSetAttribute(k_sums, cudaFuncAttributeMaxDynamicSharedMemorySize, sm1);
    cudaFuncSetAttribute(k_all,  cudaFuncAttributeMaxDynamicSharedMemorySize, sm3);

    k_sums<<<dim3(NBT * NSL, NC), NT, sm1>>>(inp, zz, W);
    k_scan<<<BH / 256, 256>>>(benc);
    k_all <<<dim3(NBT * NSL, NC), NT, sm3>>>(Vmu, Vsg, Vpi);
    k_reduce<<<BL / 8, 280>>>(bmu, bsg, bpi, out);
}

// round 10
// speedup vs baseline: 3.0653x; 1.0350x over previous
#include <cuda_runtime.h>
#include <cuda_fp16.h>
#include <cstdint>

#define Bsz 256
#define Lsz 500
#define Dsz 3
#define Csz 32
#define Isz 35
#define Hsz 512
#define Msz 5
#define Osz 15
#define Jsz 35
#define NC  50
#define LC  10
#define BH  (Bsz*Hsz)   /* 131072 */
#define BL  (Bsz*Lsz)   /* 128000 */
#define NSL 4           /* h slices */
#define HS  (Hsz/NSL)   /* 128 */
#define BT  128         /* b tile */
#define NBT (Bsz/BT)    /* 2 */
#define XP  44          /* xs row stride (floats), k_sums */
#define NT  512
#define CP  136         /* c16 smem row stride (halfs) */
#define HP2 132         /* hs row stride (words) -> 4b+k conflict-free frags */

#define WCNT (Isz*HS)   /* 4480 */
#define XCNT (BT*XP)    /* 5632 */

// k_all smem byte layout (dynamic)
#define SM_VS0 0                         /* V tf32 bits [128][40] = 20480 B */
#define SM_VS1 (SM_VS0 + 20480)
#define SM_HS  (SM_VS1 + 20480)          /* relu(a) tf32 bits [128][132] = 67584 B */
#define SM_C0  (SM_HS + 67584)           /* c16 stage 128*136 halfs = 34816 B */
#define SM_C1  (SM_C0 + 34816)
#define SM_RED (SM_C1 + 34816)           /* K-half reduce buf [128][40] f32 = 20480 B */
#define SM_TOT (SM_RED + 20480)          /* 198656 B */

// ONE extern dynamic-smem symbol for the whole TU
extern __shared__ __align__(16) char dyn_smem[];

// Scratch
__device__ __align__(16) float  g_S[(size_t)NC * BH];
__device__ __align__(16) float  g_P[(size_t)NC * BH];
__device__ __align__(16) float  g_part[(size_t)NSL * BL * 40];
__device__ __align__(16) __half g_c16[(size_t)Lsz * BH];

using u64 = unsigned long long;

__device__ __forceinline__ u64 splat2(float x) {
    u64 r; unsigned u = __float_as_uint(x);
    asm("mov.b64 %0, {%1, %1};" : "=l"(r) : "r"(u));
    return r;
}
__device__ __forceinline__ u64 fma2(u64 a, u64 b, u64 c) {
    u64 d; asm("fma.rn.f32x2 %0, %1, %2, %3;" : "=l"(d) : "l"(a), "l"(b), "l"(c));
    return d;
}
__device__ __forceinline__ u64 add2(u64 a, u64 b) {
    u64 d; asm("add.rn.f32x2 %0, %1, %2;" : "=l"(d) : "l"(a), "l"(b));
    return d;
}
__device__ __forceinline__ void cp16(unsigned dst, const void* src) {
    asm volatile("cp.async.ca.shared.global [%0], [%1], 16;" :: "r"(dst), "l"(src));
}
__device__ __forceinline__ void cp4(unsigned dst, const void* src) {
    asm volatile("cp.async.ca.shared.global [%0], [%1], 4;" :: "r"(dst), "l"(src));
}
__device__ __forceinline__ void cp_commit() { asm volatile("cp.async.commit_group;"); }
__device__ __forceinline__ void cp_wait0()  { asm volatile("cp.async.wait_group 0;"); }
__device__ __forceinline__ unsigned f2tf32(float x) {
    unsigned r; asm("cvt.rna.tf32.f32 %0, %1;" : "=r"(r) : "f"(x)); return r;
}
// m16n8k8 tf32 HMMA (plain sm_80+ PTX -- works on the harness's sm_103 target)
__device__ __forceinline__ void mma_tf32(float d[4],
                                         unsigned a0, unsigned a1, unsigned a2, unsigned a3,
                                         unsigned b0, unsigned b1) {
    asm volatile(
        "mma.sync.aligned.m16n8k8.row.col.f32.tf32.tf32.f32 "
        "{%0,%1,%2,%3}, {%4,%5,%6,%7}, {%8,%9}, {%0,%1,%2,%3};"
        : "+f"(d[0]), "+f"(d[1]), "+f"(d[2]), "+f"(d[3])
        : "r"(a0), "r"(a1), "r"(a2), "r"(a3), "r"(b0), "r"(b1));
}

// ---------------------------------------------------------------------------
// k_sums: the encoder, fp32 chunk sums + fp16 c store. (unchanged, known-good)
// ---------------------------------------------------------------------------
__device__ __forceinline__ void stage_wx_async(unsigned ws_a, unsigned xs_a,
                                               const float* __restrict__ W,
                                               const float* __restrict__ inp,
                                               const float* __restrict__ zz,
                                               int l, int h0, int b0, int tid)
{
    const float4* wsrc = (const float4*)(W + (size_t)l * (Isz * Hsz)) + (h0 >> 2);
#pragma unroll
    for (int q = 0; q < 3; q++) {
        int idx = tid + NT * q;
        if (idx < Isz * 32) {
            int row = idx >> 5, col = idx & 31;
            cp16(ws_a + (unsigned)(row * 32 + col) * 16, wsrc + row * 128 + col);
        }
    }
#pragma unroll
    for (int q = 0; q < 2; q++) {
        int idx = tid + NT * q;
        int b = idx >> 3, qf = idx & 7;
        cp16(xs_a + (unsigned)(b * XP + 4 + qf * 4) * 4,
             zz + (size_t)(b0 + b) * (Lsz * Csz) + (size_t)l * Csz + qf * 4);
    }
    if (tid < BT * Dsz) {
        int b = tid / Dsz, i = tid % Dsz;
        cp4(xs_a + (unsigned)(b * XP + i) * 4,
            inp + (size_t)(b0 + b) * (Lsz * Dsz) + (size_t)l * Dsz + i);
    }
}

__device__ __forceinline__ void encode_step(u64 c2[4][4], const float* ws,
                                            const float* xs, int bg, int hg)
{
#pragma unroll
    for (int r = 0; r < 4; r++)
#pragma unroll
        for (int p = 0; p < 4; p++) c2[r][p] = 0ull;
#pragma unroll
    for (int i = 0; i < Isz; i++) {
        const int xc = (i < Dsz) ? i : i + 1;
        u64 xa[4], wv[4];
#pragma unroll
        for (int r = 0; r < 4; r++) xa[r] = splat2(xs[(bg * 4 + r) * XP + xc]);
#pragma unroll
        for (int p = 0; p < 4; p++) wv[p] = *(const u64*)&ws[i * HS + hg * 2 + 32 * p];
#pragma unroll
        for (int r = 0; r < 4; r++)
#pragma unroll
            for (int p = 0; p < 4; p++) c2[r][p] = fma2(xa[r], wv[p], c2[r][p]);
    }
}

__global__ void __launch_bounds__(NT) k_sums(const float* __restrict__ inp,
                                             const float* __restrict__ zz,
                                             const float* __restrict__ W)
{
    float* smem = (float*)dyn_smem;
    float* ws[2] = { smem, smem + WCNT };
    float* xs[2] = { smem + 2 * WCNT, smem + 2 * WCNT + XCNT };
    const unsigned sbase = (unsigned)__cvta_generic_to_shared(dyn_smem);
    const unsigned ws_a[2] = { sbase, sbase + WCNT * 4u };
    const unsigned xs_a[2] = { sbase + 2u * WCNT * 4u, sbase + (2u * WCNT + XCNT) * 4u };

    const int tid = threadIdx.x;
    const int b0  = (blockIdx.x / NSL) * BT;
    const int h0  = (blockIdx.x % NSL) * HS;
    const int k   = blockIdx.y;
    const int bg  = tid >> 4, hg = tid & 15;

    u64 acc[4][4];
#pragma unroll
    for (int r = 0; r < 4; r++)
#pragma unroll
        for (int p = 0; p < 4; p++) acc[r][p] = 0ull;

    stage_wx_async(ws_a[0], xs_a[0], W, inp, zz, k * LC, h0, b0, tid);
    cp_commit(); cp_wait0();
    __syncthreads();

    for (int t = 0; t < LC; t++) {
        const int l = k * LC + t;
        const int cur = t & 1, nxt = cur ^ 1;
        if (t + 1 < LC) {
            stage_wx_async(ws_a[nxt], xs_a[nxt], W, inp, zz, l + 1, h0, b0, tid);
            cp_commit();
        }
        u64 c2[4][4];
        encode_step(c2, ws[cur], xs[cur], bg, hg);
#pragma unroll
        for (int r = 0; r < 4; r++) {
            __half* crow = g_c16 + ((size_t)l * Bsz + b0 + bg * 4 + r) * Hsz + h0;
#pragma unroll
            for (int p = 0; p < 4; p++) {
                acc[r][p] = add2(acc[r][p], c2[r][p]);
                float2 f = *(float2*)&c2[r][p];
                *(__half2*)&crow[hg * 2 + 32 * p] = __floats2half2_rn(f.x, f.y);
            }
        }
        cp_wait0();
        __syncthreads();
    }

    float* sb = g_S + (size_t)k * BH + (size_t)b0 * Hsz + h0;
#pragma unroll
    for (int r = 0; r < 4; r++)
#pragma unroll
        for (int p = 0; p < 4; p++)
            *(u64*)&sb[(size_t)(bg * 4 + r) * Hsz + hg * 2 + 32 * p] = acc[r][p];
}

__global__ void k_scan(const float* __restrict__ benc)
{
    const int idx = blockIdx.x * 256 + threadIdx.x;
    float run = benc[idx & (Hsz - 1)];
#pragma unroll 5
    for (int k = 0; k < NC; k++) {
        g_P[(size_t)k * BH + idx] = run;
        run += g_S[(size_t)k * BH + idx];
    }
}

// ---------------------------------------------------------------------------
// k_all: prefix (registers, fed by staged c16) + HMMA tf32 decode.
// Block = (btile*NSL + slice, chunk). 512 threads = 16 warps:
//   warp = (kh = wid>>3) K-half x (sb = wid&7) 16-row b strip.
// Per step: stage next c16/V; 40x mma.m16n8k8 per warp from hs/vs (tf32 bits);
// kh=1 writes partial D to red smem; sync; kh=0 adds + stores g_part;
// acc += c16; publish relu(acc) as tf32 into hs.
// ---------------------------------------------------------------------------
__global__ void __launch_bounds__(NT) k_all(const float* __restrict__ Vmu,
                                            const float* __restrict__ Vsg,
                                            const float* __restrict__ Vpi)
{
    char* smem = dyn_smem;
    const unsigned sbase = (unsigned)__cvta_generic_to_shared(dyn_smem);
    unsigned* vs_u[2] = { (unsigned*)(smem + SM_VS0), (unsigned*)(smem + SM_VS1) };
    unsigned* hs_u    = (unsigned*)(smem + SM_HS);
    __half*   cs[2]   = { (__half*)(smem + SM_C0), (__half*)(smem + SM_C1) };
    float*    redp    = (float*)(smem + SM_RED);
    const unsigned cs_a[2] = { sbase + SM_C0, sbase + SM_C1 };

    const int tid = threadIdx.x;
    const int wid = tid >> 5, lane = tid & 31;
    const int b0  = (blockIdx.x / NSL) * BT;
    const int s   = blockIdx.x % NSL;
    const int h0  = s * HS;
    const int k   = blockIdx.y;
    const int bg  = tid >> 4, hg = tid & 15;   // acc owner: 4b x 8h
    const int sb  = wid & 7;                   // b strip (16 rows)
    const int kh  = wid >> 3;                  // K half (64 h)
    const int rbase = sb * 16 + (lane >> 2);   // D fragment row
    const int kl  = lane & 3;

    // V staging descriptors: u = tid + 512q -> (h = u/40, jc = u%40)
    unsigned vq[10], bdst[10];
#pragma unroll
    for (int q = 0; q < 10; q++) {
        int u = tid + NT * q;
        int h = u / 40, jc = u % 40;
        unsigned tag, off;
        if (jc < 15)      { tag = 0u; off = (h0 + h) * Osz + jc; }
        else if (jc < 30) { tag = 1u; off = (h0 + h) * Osz + (jc - 15); }
        else if (jc < 35) { tag = 2u; off = (h0 + h) * Msz + (jc - 30); }
        else              { tag = 3u; off = 0; }
        vq[q] = (tag << 30) | off;
        bdst[q] = (unsigned)(h * 40 + jc);
    }

    auto load_V = [&](int l, unsigned vreg[10]) {
        const size_t lmu = (size_t)l * (Hsz * Osz);
        const size_t lpi = (size_t)l * (Hsz * Msz);
#pragma unroll
        for (int q = 0; q < 10; q++) {
            unsigned tag = vq[q] >> 30, off = vq[q] & 0x3FFFFFFFu;
            float v = 0.0f;
            if (tag == 0u)      v = Vmu[lmu + off];
            else if (tag == 1u) v = Vsg[lmu + off];
            else if (tag == 2u) v = Vpi[lpi + off];
            vreg[q] = f2tf32(v);
        }
    };
    auto stage_c = [&](int l, unsigned ca) {
#pragma unroll
        for (int q = 0; q < 4; q++) {
            int idx = tid + NT * q;
            int row = idx >> 4, ch = idx & 15;
            cp16(ca + (unsigned)(row * CP + ch * 8) * 2,
                 g_c16 + ((size_t)l * Bsz + b0 + row) * Hsz + h0 + ch * 8);
        }
        cp_commit();
    };
    auto publish_A = [&](u64 acc[4][4]) {
#pragma unroll
        for (int r = 0; r < 4; r++) {
            const int b = bg * 4 + r;
#pragma unroll
            for (int p = 0; p < 4; p++) {
                float2 v = *(float2*)&acc[r][p];
                unsigned lo = f2tf32(fmaxf(v.x, 0.0f));
                unsigned hi = f2tf32(fmaxf(v.y, 0.0f));
                u64 pk; asm("mov.b64 %0, {%1, %2};" : "=l"(pk) : "r"(lo), "r"(hi));
                *(u64*)&hs_u[b * HP2 + hg * 2 + 32 * p] = pk;
            }
        }
    };

    // prologue: stage step-0 c16 + V, init acc from carry P, publish relu(a[l0])
    stage_c(k * LC, cs_a[0]);
    {
        unsigned v0[10];
        load_V(k * LC, v0);
#pragma unroll
        for (int q = 0; q < 10; q++) vs_u[0][bdst[q]] = v0[q];
    }
    u64 acc[4][4];
    {
        const float* P = g_P + (size_t)k * BH + (size_t)b0 * Hsz + h0;
#pragma unroll
        for (int r = 0; r < 4; r++)
#pragma unroll
            for (int p = 0; p < 4; p++) {
                float2 v = *(const float2*)&P[(size_t)(bg * 4 + r) * Hsz + hg * 2 + 32 * p];
                acc[r][p] = *(const u64*)&v;
            }
    }
    publish_A(acc);
    cp_wait0();
    __syncthreads();

    for (int t = 0; t < LC; t++) {
        const int l = k * LC + t;
        const int cur = t & 1, nxt = cur ^ 1;

        // 1) issue next-step staging (c16 async; V into regs)
        unsigned vreg[10];
        if (t + 1 < LC) {
            stage_c(l + 1, cs_a[nxt]);
            load_V(l + 1, vreg);
        }

        // 2) HMMA decode: D[16b x 40j] over this warp's 64-h half
        float d[5][4];
#pragma unroll
        for (int n = 0; n < 5; n++)
#pragma unroll
            for (int u = 0; u < 4; u++) d[n][u] = 0.0f;

        const unsigned* vcur = vs_u[cur];
#pragma unroll
        for (int kc = 0; kc < 8; kc++) {
            const int k0 = kh * 64 + kc * 8;
            unsigned a0 = hs_u[rbase * HP2 + k0 + kl];
            unsigned a1 = hs_u[(rbase + 8) * HP2 + k0 + kl];
            unsigned a2 = hs_u[rbase * HP2 + k0 + 4 + kl];
            unsigned a3 = hs_u[(rbase + 8) * HP2 + k0 + 4 + kl];
#pragma unroll
            for (int n = 0; n < 5; n++) {
                unsigned bf0 = vcur[(k0 + kl) * 40 + n * 8 + (lane >> 2)];
                unsigned bf1 = vcur[(k0 + 4 + kl) * 40 + n * 8 + (lane >> 2)];
                mma_tf32(d[n], a0, a1, a2, a3, bf0, bf1);
            }
        }

        // 3) K-half 1 publishes its partials to red
        if (kh) {
#pragma unroll
            for (int n = 0; n < 5; n++) {
                *(float2*)&redp[rbase * 40 + n * 8 + 2 * kl]       = make_float2(d[n][0], d[n][1]);
                *(float2*)&redp[(rbase + 8) * 40 + n * 8 + 2 * kl] = make_float2(d[n][2], d[n][3]);
            }
        }

        // 4) recurrence: a += c16[l]
        {
            const __half* cb = cs[cur];
#pragma unroll
            for (int r = 0; r < 4; r++)
#pragma unroll
                for (int p = 0; p < 4; p++) {
                    __half2 h2 = *(const __half2*)&cb[(bg * 4 + r) * CP + hg * 2 + 32 * p];
                    float2 c = __half22float2(h2);
                    float2 a = *(float2*)&acc[r][p];
                    a.x += c.x; a.y += c.y;
                    acc[r][p] = *(u64*)&a;
                }
        }

        __syncthreads();   // mma reads of hs/vs done; red visible

        // 5) K-half 0 adds red + stores g_part
        if (!kh) {
            float* dstb = g_part + ((size_t)s * BL + (size_t)l * Bsz + b0) * 40;
#pragma unroll
            for (int n = 0; n < 5; n++) {
                const int j = n * 8 + 2 * kl;
                float2 r0 = *(float2*)&redp[rbase * 40 + j];
                float2 r1 = *(float2*)&redp[(rbase + 8) * 40 + j];
                *(float2*)&dstb[(size_t)rbase * 40 + j] =
                    make_float2(d[n][0] + r0.x, d[n][1] + r0.y);
                *(float2*)&dstb[(size_t)(rbase + 8) * 40 + j] =
                    make_float2(d[n][2] + r1.x, d[n][3] + r1.y);
            }
        }

        // 6) publish relu(a[l+1]); store next V; drain cp.async
        publish_A(acc);
        if (t + 1 < LC) {
#pragma unroll
            for (int q = 0; q < 10; q++) vs_u[nxt][bdst[q]] = vreg[q];
            cp_wait0();
        }
        __syncthreads();
    }
}

// ---------------------------------------------------------------------------
// k_reduce: sum slices + output biases. g_part layout [s][l*B + b][40].
// ---------------------------------------------------------------------------
__global__ void __launch_bounds__(280) k_reduce(const float* __restrict__ bmu,
                                                const float* __restrict__ bsg,
                                                const float* __restrict__ bpi,
                                                float* __restrict__ out)
{
    const int p = threadIdx.x / 35;
    const int j = threadIdx.x % 35;
    const size_t pr = (size_t)blockIdx.x * 8 + p;
    const int l = (int)(pr >> 8);
    const int b = (int)(pr & 255);

    float v = 0.0f;
#pragma unroll
    for (int s = 0; s < NSL; s++)
        v += g_part[((size_t)s * BL + pr) * 40 + j];

    float bias;
    if (j < 15)      bias = bmu[l * Osz + j];
    else if (j < 30) bias = bsg[l * Osz + (j - 15)];
    else             bias = bpi[l * Msz + (j - 30)];

    out[((size_t)b * Lsz + l) * Jsz + j] = v + bias;
}

// ---------------------------------------------------------------------------
extern "C" void kernel_launch(void* const* d_in, const int* in_sizes, int n_in,
                              void* d_out, int out_size)
{
    const float* inp  = (const float*)d_in[0];
    const float* zz   = (const float*)d_in[1];
    const float* W    = (const float*)d_in[2];
    const float* benc = (const float*)d_in[3];
    const float* Vmu  = (const float*)d_in[4];
    const float* bmu  = (const float*)d_in[5];
    const float* Vsg  = (const float*)d_in[6];
    const float* bsg  = (const float*)d_in[7];
    const float* Vpi  = (const float*)d_in[8];
    const float* bpi  = (const float*)d_in[9];
    float* out = (float*)d_out;

    const int sm1 = (2 * WCNT + 2 * XCNT) * (int)sizeof(float);   // 80.9 KB
    cudaFuncSetAttribute(k_sums, cudaFuncAttributeMaxDynamicSharedMemorySize, sm1);
    cudaFuncSetAttribute(k_all,  cudaFuncAttributeMaxDynamicSharedMemorySize, SM_TOT);

    k_sums<<<dim3(NBT * NSL, NC), NT, sm1>>>(inp, zz, W);
    k_scan<<<BH / 256, 256>>>(benc);
    k_all <<<dim3(NBT * NSL, NC), NT, SM_TOT>>>(Vmu, Vsg, Vpi);
    k_reduce<<<BL / 8, 280>>>(bmu, bsg, bpi, out);
}